// round 3
// baseline (speedup 1.0000x reference)
#include <cuda_runtime.h>
#include <math.h>

#define BATCH 16
#define CH    512
#define TT    1024
#define NHEAD 8

// ---------------- scratch (static device allocations are allowed) ----------
__device__ float g_mean[BATCH * 32];
__device__ float g_rstd[BATCH * 32];
__device__ float g_qkv[(size_t)BATCH * 3 * CH * TT];   // 96 MB
__device__ float g_h  [(size_t)BATCH * CH * TT];       // 32 MB

// ---------------- GroupNorm statistics -------------------------------------
// one block per (b, g); group = 16 channels x 1024 = 16384 contiguous floats
__global__ void gn_stats_kernel(const float* __restrict__ x) {
    const int bg = blockIdx.x;                       // b*32 + g
    const float4* base = (const float4*)(x + (size_t)bg * 16 * TT);
    float s = 0.f, ss = 0.f;
    for (int i = threadIdx.x; i < 4096; i += 256) {
        float4 v = base[i];
        s  += v.x + v.y + v.z + v.w;
        ss += v.x*v.x + v.y*v.y + v.z*v.z + v.w*v.w;
    }
    #pragma unroll
    for (int o = 16; o; o >>= 1) {
        s  += __shfl_down_sync(0xffffffffu, s,  o);
        ss += __shfl_down_sync(0xffffffffu, ss, o);
    }
    __shared__ float sh[16];
    const int w = threadIdx.x >> 5, l = threadIdx.x & 31;
    if (l == 0) { sh[w] = s; sh[8 + w] = ss; }
    __syncthreads();
    if (threadIdx.x == 0) {
        float S = 0.f, SS = 0.f;
        #pragma unroll
        for (int i = 0; i < 8; i++) { S += sh[i]; SS += sh[8 + i]; }
        const float mean = S * (1.f / 16384.f);
        const float var  = SS * (1.f / 16384.f) - mean * mean;
        g_mean[bg] = mean;
        g_rstd[bg] = rsqrtf(var + 1e-5f);
    }
}

// ---------------- QKV GEMM with fused GroupNorm on B-tile ------------------
// out[b,m,t] = sum_c W[m,c] * gn(x)[b,c,t] + bias[m];  M=1536,N=1024,K=512
__global__ __launch_bounds__(256, 2)
void qkv_gemm_kernel(const float* __restrict__ x,
                     const float* __restrict__ nw,
                     const float* __restrict__ nb,
                     const float* __restrict__ W,
                     const float* __restrict__ bias) {
    __shared__ float As[16][132];
    __shared__ float Bs[16][132];
    const int b  = blockIdx.z;
    const int m0 = blockIdx.y * 128, n0 = blockIdx.x * 128;
    const int tid = threadIdx.x, tx = tid & 15, ty = tid >> 4;
    const float* xb = x + (size_t)b * CH * TT;
    float* out = g_qkv + (size_t)b * 3 * CH * TT;

    float acc[8][8];
    #pragma unroll
    for (int i = 0; i < 8; i++)
        #pragma unroll
        for (int j = 0; j < 8; j++) acc[i][j] = 0.f;

    for (int k0 = 0; k0 < CH; k0 += 16) {
        // A tile: W[m0..m0+127][k0..k0+15] -> As[k][m]
        #pragma unroll
        for (int f = tid; f < 512; f += 256) {
            const int row = f >> 2, k4 = (f & 3) << 2;
            float4 a = *(const float4*)(W + (size_t)(m0 + row) * CH + k0 + k4);
            As[k4 + 0][row] = a.x; As[k4 + 1][row] = a.y;
            As[k4 + 2][row] = a.z; As[k4 + 3][row] = a.w;
        }
        // B tile: groupnorm(x)[c][t], c = k0+r
        #pragma unroll
        for (int f = tid; f < 512; f += 256) {
            const int r = f >> 5, t4 = (f & 31) << 2;
            const int c = k0 + r;
            float4 v = *(const float4*)(xb + (size_t)c * TT + n0 + t4);
            const int bg = (b << 5) + (c >> 4);
            const float rsd = g_rstd[bg];
            const float wc  = nw[c] * rsd;
            const float bc  = fmaf(-g_mean[bg], wc, nb[c]);
            float* dst = &Bs[r][t4];
            dst[0] = fmaf(v.x, wc, bc); dst[1] = fmaf(v.y, wc, bc);
            dst[2] = fmaf(v.z, wc, bc); dst[3] = fmaf(v.w, wc, bc);
        }
        __syncthreads();
        #pragma unroll
        for (int k = 0; k < 16; k++) {
            float4 a0 = *(const float4*)&As[k][ty * 4];
            float4 a1 = *(const float4*)&As[k][64 + ty * 4];
            float4 b0 = *(const float4*)&Bs[k][tx * 4];
            float4 b1 = *(const float4*)&Bs[k][64 + tx * 4];
            float ar[8] = {a0.x, a0.y, a0.z, a0.w, a1.x, a1.y, a1.z, a1.w};
            float br[8] = {b0.x, b0.y, b0.z, b0.w, b1.x, b1.y, b1.z, b1.w};
            #pragma unroll
            for (int i = 0; i < 8; i++)
                #pragma unroll
                for (int j = 0; j < 8; j++) acc[i][j] = fmaf(ar[i], br[j], acc[i][j]);
        }
        __syncthreads();
    }
    #pragma unroll
    for (int ri = 0; ri < 2; ri++)
        #pragma unroll
        for (int i = 0; i < 4; i++) {
            const int m = m0 + ri * 64 + ty * 4 + i;
            const float bi = bias[m];
            float* orow = out + (size_t)m * TT + n0;
            #pragma unroll
            for (int rj = 0; rj < 2; rj++) {
                float4 v;
                v.x = acc[ri * 4 + i][rj * 4 + 0] + bi;
                v.y = acc[ri * 4 + i][rj * 4 + 1] + bi;
                v.z = acc[ri * 4 + i][rj * 4 + 2] + bi;
                v.w = acc[ri * 4 + i][rj * 4 + 3] + bi;
                *(float4*)(orow + rj * 64 + tx * 4) = v;
            }
        }
}

// ---------------- Flash attention (fp32, online softmax) -------------------
// per block: one 64-query tile of one head of one batch element.
// qkv layout rows per head h: q = h*192 + c, k = h*192+64+c, v = h*192+128+c
#define SW 68
__global__ void attn_kernel() {
    extern __shared__ float sm[];
    float* Qs = sm;                 // [64][SW]  (c, t), pre-scaled by 0.125
    float* Ks = Qs + 64 * SW;       // [64][SW]  (c, s)
    float* Vs = Ks + 64 * SW;       // [64][SW]  (c, s)
    float* Ps = Vs + 64 * SW;       // [64][SW]  (s, t)
    float* Cs = Ps + 64 * SW;       // [64] per-t correction factor
    float* Ls = Cs + 64;            // [64] per-t softmax denominator

    const int tid = threadIdx.x;
    const int tx = tid & 15, ty = tid >> 4;
    const int tblk = blockIdx.x, head = blockIdx.y, b = blockIdx.z;

    const size_t base = ((size_t)b * (3 * CH) + (size_t)head * 192) * TT;
    const float* qp  = g_qkv + base + (size_t)tblk * 64;
    const float* kp0 = g_qkv + base + (size_t)64 * TT;

    #pragma unroll
    for (int f = tid; f < 1024; f += 256) {
        const int c = f >> 4, t4 = (f & 15) << 2;
        float4 v = *(const float4*)(qp + (size_t)c * TT + t4);
        float* d = Qs + c * SW + t4;
        d[0] = v.x * 0.125f; d[1] = v.y * 0.125f;
        d[2] = v.z * 0.125f; d[3] = v.w * 0.125f;
    }

    float m_i[4], l_i[4], O[4][4];   // O is [c][t]: c = ty*4+i, t = tx*4+j
    #pragma unroll
    for (int i = 0; i < 4; i++) {
        m_i[i] = -1e30f; l_i[i] = 0.f;
        #pragma unroll
        for (int j = 0; j < 4; j++) O[i][j] = 0.f;
    }

    for (int sb = 0; sb < 16; sb++) {
        __syncthreads();   // orders Q load (iter 0) / prior O-phase reads (iters>0)
        const float* kp = kp0 + sb * 64;
        #pragma unroll
        for (int f = tid; f < 1024; f += 256) {
            const int c = f >> 4, s4 = (f & 15) << 2;
            float4 kv = *(const float4*)(kp + (size_t)c * TT + s4);
            float4 vv = *(const float4*)(kp + (size_t)(64 + c) * TT + s4);
            float* kd = Ks + c * SW + s4;
            kd[0] = kv.x; kd[1] = kv.y; kd[2] = kv.z; kd[3] = kv.w;
            float* vd = Vs + c * SW + s4;
            vd[0] = vv.x; vd[1] = vv.y; vd[2] = vv.z; vd[3] = vv.w;
        }
        __syncthreads();

        // S[t][s], t = ty*4+i, s = tx*4+j
        float S[4][4];
        #pragma unroll
        for (int i = 0; i < 4; i++)
            #pragma unroll
            for (int j = 0; j < 4; j++) S[i][j] = 0.f;

        #pragma unroll 16
        for (int c = 0; c < 64; c++) {
            float4 qa = *(const float4*)(Qs + c * SW + ty * 4);
            float4 ka = *(const float4*)(Ks + c * SW + tx * 4);
            float qr[4] = {qa.x, qa.y, qa.z, qa.w};
            float kr[4] = {ka.x, ka.y, ka.z, ka.w};
            #pragma unroll
            for (int i = 0; i < 4; i++)
                #pragma unroll
                for (int j = 0; j < 4; j++) S[i][j] = fmaf(qr[i], kr[j], S[i][j]);
        }

        // online softmax per t-row; 16 lanes sharing ty reduce over s
        #pragma unroll
        for (int i = 0; i < 4; i++) {
            float rm = fmaxf(fmaxf(S[i][0], S[i][1]), fmaxf(S[i][2], S[i][3]));
            rm = fmaxf(rm, __shfl_xor_sync(0xffffffffu, rm, 8));
            rm = fmaxf(rm, __shfl_xor_sync(0xffffffffu, rm, 4));
            rm = fmaxf(rm, __shfl_xor_sync(0xffffffffu, rm, 2));
            rm = fmaxf(rm, __shfl_xor_sync(0xffffffffu, rm, 1));
            const float mn   = fmaxf(m_i[i], rm);
            const float corr = __expf(m_i[i] - mn);
            m_i[i] = mn;
            float rs = 0.f;
            #pragma unroll
            for (int j = 0; j < 4; j++) { S[i][j] = __expf(S[i][j] - mn); rs += S[i][j]; }
            rs += __shfl_xor_sync(0xffffffffu, rs, 8);
            rs += __shfl_xor_sync(0xffffffffu, rs, 4);
            rs += __shfl_xor_sync(0xffffffffu, rs, 2);
            rs += __shfl_xor_sync(0xffffffffu, rs, 1);
            l_i[i] = l_i[i] * corr + rs;
            if (tx == 0) Cs[ty * 4 + i] = corr;
            #pragma unroll
            for (int j = 0; j < 4; j++)
                Ps[(tx * 4 + j) * SW + ty * 4 + i] = S[i][j];   // P as [s][t]
        }
        __syncthreads();

        // O[c][t] = O[c][t]*corr[t] + sum_s V[c][s] * P[s][t]
        float4 cc = *(const float4*)(Cs + tx * 4);
        float cr[4] = {cc.x, cc.y, cc.z, cc.w};
        #pragma unroll
        for (int i = 0; i < 4; i++)
            #pragma unroll
            for (int j = 0; j < 4; j++) O[i][j] *= cr[j];

        #pragma unroll 16
        for (int s = 0; s < 64; s++) {
            float4 pb = *(const float4*)(Ps + s * SW + tx * 4);
            float pr[4] = {pb.x, pb.y, pb.z, pb.w};
            float vr[4];
            #pragma unroll
            for (int i = 0; i < 4; i++) vr[i] = Vs[(ty * 4 + i) * SW + s];
            #pragma unroll
            for (int i = 0; i < 4; i++)
                #pragma unroll
                for (int j = 0; j < 4; j++) O[i][j] = fmaf(vr[i], pr[j], O[i][j]);
        }
    }

    if (tx == 0) {
        #pragma unroll
        for (int i = 0; i < 4; i++) Ls[ty * 4 + i] = l_i[i];
    }
    __syncthreads();
    float4 lv = *(const float4*)(Ls + tx * 4);
    const float linv[4] = {1.f / lv.x, 1.f / lv.y, 1.f / lv.z, 1.f / lv.w};

    float* hp = g_h + ((size_t)b * CH + (size_t)head * 64) * TT + (size_t)tblk * 64;
    #pragma unroll
    for (int i = 0; i < 4; i++) {
        float4 v;
        v.x = O[i][0] * linv[0]; v.y = O[i][1] * linv[1];
        v.z = O[i][2] * linv[2]; v.w = O[i][3] * linv[3];
        *(float4*)(hp + (size_t)(ty * 4 + i) * TT + tx * 4) = v;
    }
}

// ---------------- Proj GEMM + bias + residual ------------------------------
// out[b,m,t] = sum_c W[m,c] * h[b,c,t] + bias[m] + x[b,m,t]
__global__ __launch_bounds__(256, 2)
void proj_gemm_kernel(const float* __restrict__ W,
                      const float* __restrict__ bias,
                      const float* __restrict__ x,
                      float* __restrict__ outp) {
    __shared__ float As[16][132];
    __shared__ float Bs[16][132];
    const int b  = blockIdx.z;
    const int m0 = blockIdx.y * 128, n0 = blockIdx.x * 128;
    const int tid = threadIdx.x, tx = tid & 15, ty = tid >> 4;
    const float* hb = g_h + (size_t)b * CH * TT;
    const float* xb = x + (size_t)b * CH * TT;
    float* ob = outp + (size_t)b * CH * TT;

    float acc[8][8];
    #pragma unroll
    for (int i = 0; i < 8; i++)
        #pragma unroll
        for (int j = 0; j < 8; j++) acc[i][j] = 0.f;

    for (int k0 = 0; k0 < CH; k0 += 16) {
        #pragma unroll
        for (int f = tid; f < 512; f += 256) {
            const int row = f >> 2, k4 = (f & 3) << 2;
            float4 a = *(const float4*)(W + (size_t)(m0 + row) * CH + k0 + k4);
            As[k4 + 0][row] = a.x; As[k4 + 1][row] = a.y;
            As[k4 + 2][row] = a.z; As[k4 + 3][row] = a.w;
        }
        #pragma unroll
        for (int f = tid; f < 512; f += 256) {
            const int r = f >> 5, t4 = (f & 31) << 2;
            float4 v = *(const float4*)(hb + (size_t)(k0 + r) * TT + n0 + t4);
            float* dst = &Bs[r][t4];
            dst[0] = v.x; dst[1] = v.y; dst[2] = v.z; dst[3] = v.w;
        }
        __syncthreads();
        #pragma unroll
        for (int k = 0; k < 16; k++) {
            float4 a0 = *(const float4*)&As[k][ty * 4];
            float4 a1 = *(const float4*)&As[k][64 + ty * 4];
            float4 b0 = *(const float4*)&Bs[k][tx * 4];
            float4 b1 = *(const float4*)&Bs[k][64 + tx * 4];
            float ar[8] = {a0.x, a0.y, a0.z, a0.w, a1.x, a1.y, a1.z, a1.w};
            float br[8] = {b0.x, b0.y, b0.z, b0.w, b1.x, b1.y, b1.z, b1.w};
            #pragma unroll
            for (int i = 0; i < 8; i++)
                #pragma unroll
                for (int j = 0; j < 8; j++) acc[i][j] = fmaf(ar[i], br[j], acc[i][j]);
        }
        __syncthreads();
    }
    #pragma unroll
    for (int ri = 0; ri < 2; ri++)
        #pragma unroll
        for (int i = 0; i < 4; i++) {
            const int m = m0 + ri * 64 + ty * 4 + i;
            const float bi = bias[m];
            #pragma unroll
            for (int rj = 0; rj < 2; rj++) {
                const size_t off = (size_t)m * TT + n0 + rj * 64 + tx * 4;
                float4 xr = *(const float4*)(xb + off);
                float4 v;
                v.x = acc[ri * 4 + i][rj * 4 + 0] + bi + xr.x;
                v.y = acc[ri * 4 + i][rj * 4 + 1] + bi + xr.y;
                v.z = acc[ri * 4 + i][rj * 4 + 2] + bi + xr.z;
                v.w = acc[ri * 4 + i][rj * 4 + 3] + bi + xr.w;
                *(float4*)(ob + off) = v;
            }
        }
}

// ---------------- launch ----------------------------------------------------
extern "C" void kernel_launch(void* const* d_in, const int* in_sizes, int n_in,
                              void* d_out, int out_size) {
    const float* x    = (const float*)d_in[0];
    const float* nw   = (const float*)d_in[1];
    const float* nb   = (const float*)d_in[2];
    const float* qkvw = (const float*)d_in[3];
    const float* qkvb = (const float*)d_in[4];
    const float* pw   = (const float*)d_in[5];
    const float* pb   = (const float*)d_in[6];
    float* out = (float*)d_out;

    const int attn_smem = (4 * 64 * SW + 128) * (int)sizeof(float);  // 70144 B
    cudaFuncSetAttribute(attn_kernel, cudaFuncAttributeMaxDynamicSharedMemorySize,
                         attn_smem);

    gn_stats_kernel<<<BATCH * 32, 256>>>(x);
    qkv_gemm_kernel<<<dim3(TT / 128, (3 * CH) / 128, BATCH), 256>>>(x, nw, nb, qkvw, qkvb);
    attn_kernel<<<dim3(TT / 64, NHEAD, BATCH), 256, attn_smem>>>();
    proj_gemm_kernel<<<dim3(TT / 128, CH / 128, BATCH), 256>>>(pw, pb, x, out);
}

// round 5
// speedup vs baseline: 1.1055x; 1.1055x over previous
#include <cuda_runtime.h>
#include <cuda_fp16.h>
#include <math.h>
#include <stdint.h>

#define BATCH 16
#define CH    512
#define TT    1024
#define NHEAD 8

// ---------------- scratch ---------------------------------------------------
__device__ float g_mean[BATCH * 32];
__device__ float g_rstd[BATCH * 32];
__device__ float g_qkv[(size_t)BATCH * 3 * CH * TT];   // 96 MB
__device__ float g_h  [(size_t)BATCH * CH * TT];       // 32 MB

// ---------------- helpers ----------------------------------------------------
// fp32 -> (fp16 hi, fp16 lo) split of a pair; hi+lo carries ~22 mantissa bits
__device__ __forceinline__ void split2(float a, float b, uint32_t& hi, uint32_t& lo) {
    __half2 h = __floats2half2_rn(a, b);
    float2 hf = __half22float2(h);
    __half2 l = __floats2half2_rn(a - hf.x, b - hf.y);
    hi = *reinterpret_cast<uint32_t*>(&h);
    lo = *reinterpret_cast<uint32_t*>(&l);
}

__device__ __forceinline__ void mma16816(float c[4], const uint32_t a[4],
                                         const uint32_t b[2]) {
    asm volatile(
        "mma.sync.aligned.m16n8k16.row.col.f32.f16.f16.f32 "
        "{%0,%1,%2,%3}, {%4,%5,%6,%7}, {%8,%9}, {%0,%1,%2,%3};"
        : "+f"(c[0]), "+f"(c[1]), "+f"(c[2]), "+f"(c[3])
        : "r"(a[0]), "r"(a[1]), "r"(a[2]), "r"(a[3]), "r"(b[0]), "r"(b[1]));
}

// ---------------- GroupNorm statistics --------------------------------------
__global__ void gn_stats_kernel(const float* __restrict__ x) {
    const int bg = blockIdx.x;
    const float4* base = (const float4*)(x + (size_t)bg * 16 * TT);
    float s = 0.f, ss = 0.f;
    for (int i = threadIdx.x; i < 4096; i += 256) {
        float4 v = base[i];
        s  += v.x + v.y + v.z + v.w;
        ss += v.x*v.x + v.y*v.y + v.z*v.z + v.w*v.w;
    }
    #pragma unroll
    for (int o = 16; o; o >>= 1) {
        s  += __shfl_down_sync(0xffffffffu, s,  o);
        ss += __shfl_down_sync(0xffffffffu, ss, o);
    }
    __shared__ float sh[16];
    const int w = threadIdx.x >> 5, l = threadIdx.x & 31;
    if (l == 0) { sh[w] = s; sh[8 + w] = ss; }
    __syncthreads();
    if (threadIdx.x == 0) {
        float S = 0.f, SS = 0.f;
        #pragma unroll
        for (int i = 0; i < 8; i++) { S += sh[i]; SS += sh[8 + i]; }
        const float mean = S * (1.f / 16384.f);
        const float var  = SS * (1.f / 16384.f) - mean * mean;
        g_mean[bg] = mean;
        g_rstd[bg] = rsqrtf(var + 1e-5f);
    }
}

// ---------------- HMMA GEMM (split-fp16 3-term, fp32 accuracy) --------------
// D[m, t] = sum_c W[m, c] * X[c, t]  (+bias, +optional GN on X, +optional resid)
// 128x128 block tile, K-chunks of 32, register-staged smem single buffer.
#define PITCH 40   // halves per smem row (bank-conflict-free fragment loads)

template<bool FUSE_GN, bool IS_PROJ>
__global__ __launch_bounds__(256)
void mma_gemm_kernel(const float* __restrict__ Wsrc,
                     const float* __restrict__ xin,   // qkv: B input; proj: residual
                     const float* __restrict__ bias,
                     const float* __restrict__ nw,
                     const float* __restrict__ nb,
                     float* __restrict__ outp) {
    __shared__ uint16_t Ah[128 * PITCH], Al[128 * PITCH];
    __shared__ uint16_t Bh[128 * PITCH], Bl[128 * PITCH];

    const int tid = threadIdx.x;
    const int lane = tid & 31, wid = tid >> 5;
    const int g = lane >> 2, tig = lane & 3;
    const int b = blockIdx.z, m0 = blockIdx.y * 128, n0 = blockIdx.x * 128;
    const int warp_m = wid >> 2, warp_n = wid & 3;    // 2 x 4 warp grid

    const float* Xb = IS_PROJ ? (g_h + (size_t)b * CH * TT)
                              : (xin + (size_t)b * CH * TT);
    float* Ob = IS_PROJ ? (outp + (size_t)b * CH * TT)
                        : (g_qkv + (size_t)b * 3 * CH * TT);

    float acc[4][4][4];
    #pragma unroll
    for (int mi = 0; mi < 4; ++mi)
        #pragma unroll
        for (int ni = 0; ni < 4; ++ni)
            #pragma unroll
            for (int r = 0; r < 4; ++r) acc[mi][ni][r] = 0.f;

    uint32_t sAh[8], sAl[8], sBh[8], sBl[8];

    auto loadChunk = [&](int ck) {
        const int k0 = ck * 32;
        #pragma unroll
        for (int it = 0; it < 4; ++it) {
            const int f = tid + (it << 8);
            const int row = f >> 3, k4 = (f & 7) << 2;
            float4 a = *(const float4*)(Wsrc + (size_t)(m0 + row) * CH + k0 + k4);
            split2(a.x, a.y, sAh[it * 2 + 0], sAl[it * 2 + 0]);
            split2(a.z, a.w, sAh[it * 2 + 1], sAl[it * 2 + 1]);
        }
        #pragma unroll
        for (int it = 0; it < 4; ++it) {
            const int f = tid + (it << 8);
            const int t = f & 127, c = (f >> 7) << 2;   // chunk-local channels c..c+3
            float v[4];
            #pragma unroll
            for (int j = 0; j < 4; ++j)
                v[j] = Xb[(size_t)(k0 + c + j) * TT + n0 + t];
            if (FUSE_GN) {
                #pragma unroll
                for (int j = 0; j < 4; ++j) {
                    const int cg = k0 + c + j;
                    const int bg = (b << 5) + (cg >> 4);
                    const float w  = nw[cg] * g_rstd[bg];
                    const float bb = fmaf(-g_mean[bg], w, nb[cg]);
                    v[j] = fmaf(v[j], w, bb);
                }
            }
            split2(v[0], v[1], sBh[it * 2 + 0], sBl[it * 2 + 0]);
            split2(v[2], v[3], sBh[it * 2 + 1], sBl[it * 2 + 1]);
        }
    };

    auto storeChunk = [&]() {
        #pragma unroll
        for (int it = 0; it < 4; ++it) {
            const int f = tid + (it << 8);
            const int row = f >> 3, k4 = (f & 7) << 2;
            *(uint2*)&Ah[row * PITCH + k4] = make_uint2(sAh[it * 2], sAh[it * 2 + 1]);
            *(uint2*)&Al[row * PITCH + k4] = make_uint2(sAl[it * 2], sAl[it * 2 + 1]);
        }
        #pragma unroll
        for (int it = 0; it < 4; ++it) {
            const int f = tid + (it << 8);
            const int t = f & 127, c = (f >> 7) << 2;
            *(uint32_t*)&Bh[t * PITCH + c + 0] = sBh[it * 2 + 0];
            *(uint32_t*)&Bh[t * PITCH + c + 2] = sBh[it * 2 + 1];
            *(uint32_t*)&Bl[t * PITCH + c + 0] = sBl[it * 2 + 0];
            *(uint32_t*)&Bl[t * PITCH + c + 2] = sBl[it * 2 + 1];
        }
    };

    auto compute = [&]() {
        #pragma unroll
        for (int kk = 0; kk < 32; kk += 16) {
            uint32_t afh[4][4], afl[4][4];
            #pragma unroll
            for (int mi = 0; mi < 4; ++mi) {
                const int base = (warp_m * 64 + mi * 16 + g) * PITCH + kk + tig * 2;
                afh[mi][0] = *(const uint32_t*)&Ah[base];
                afh[mi][1] = *(const uint32_t*)&Ah[base + 8 * PITCH];
                afh[mi][2] = *(const uint32_t*)&Ah[base + 8];
                afh[mi][3] = *(const uint32_t*)&Ah[base + 8 * PITCH + 8];
                afl[mi][0] = *(const uint32_t*)&Al[base];
                afl[mi][1] = *(const uint32_t*)&Al[base + 8 * PITCH];
                afl[mi][2] = *(const uint32_t*)&Al[base + 8];
                afl[mi][3] = *(const uint32_t*)&Al[base + 8 * PITCH + 8];
            }
            #pragma unroll
            for (int ni = 0; ni < 4; ++ni) {
                const int base = (warp_n * 32 + ni * 8 + g) * PITCH + kk + tig * 2;
                uint32_t bfh[2], bfl[2];
                bfh[0] = *(const uint32_t*)&Bh[base];
                bfh[1] = *(const uint32_t*)&Bh[base + 8];
                bfl[0] = *(const uint32_t*)&Bl[base];
                bfl[1] = *(const uint32_t*)&Bl[base + 8];
                #pragma unroll
                for (int mi = 0; mi < 4; ++mi) {
                    mma16816(acc[mi][ni], afh[mi], bfh);
                    mma16816(acc[mi][ni], afl[mi], bfh);
                    mma16816(acc[mi][ni], afh[mi], bfl);
                }
            }
        }
    };

    loadChunk(0);
    storeChunk();
    __syncthreads();
    for (int ck = 0; ck < 16; ++ck) {
        if (ck < 15) loadChunk(ck + 1);
        compute();
        __syncthreads();
        if (ck < 15) { storeChunk(); __syncthreads(); }
    }

    // ---- epilogue: fragment layout c0,c1=(g,2t..+1)  c2,c3=(g+8,2t..+1)
    const int mbase = m0 + warp_m * 64;
    const int nbase = n0 + warp_n * 32;
    const float* xres = IS_PROJ ? (xin + (size_t)b * CH * TT) : nullptr;
    #pragma unroll
    for (int mi = 0; mi < 4; ++mi) {
        const int mA = mbase + mi * 16 + g;
        const int mB = mA + 8;
        const float biA = bias[mA], biB = bias[mB];
        #pragma unroll
        for (int ni = 0; ni < 4; ++ni) {
            const int t = nbase + ni * 8 + tig * 2;
            float2 v0, v1;
            v0.x = acc[mi][ni][0] + biA; v0.y = acc[mi][ni][1] + biA;
            v1.x = acc[mi][ni][2] + biB; v1.y = acc[mi][ni][3] + biB;
            if (IS_PROJ) {
                float2 r0 = *(const float2*)(xres + (size_t)mA * TT + t);
                float2 r1 = *(const float2*)(xres + (size_t)mB * TT + t);
                v0.x += r0.x; v0.y += r0.y;
                v1.x += r1.x; v1.y += r1.y;
            }
            *(float2*)(Ob + (size_t)mA * TT + t) = v0;
            *(float2*)(Ob + (size_t)mB * TT + t) = v1;
        }
    }
}

// ---------------- Flash attention (fp32, online softmax) — unchanged -------
#define SW 68
__global__ void attn_kernel() {
    extern __shared__ float sm[];
    float* Qs = sm;
    float* Ks = Qs + 64 * SW;
    float* Vs = Ks + 64 * SW;
    float* Ps = Vs + 64 * SW;
    float* Cs = Ps + 64 * SW;
    float* Ls = Cs + 64;

    const int tid = threadIdx.x;
    const int tx = tid & 15, ty = tid >> 4;
    const int tblk = blockIdx.x, head = blockIdx.y, b = blockIdx.z;

    const size_t base = ((size_t)b * (3 * CH) + (size_t)head * 192) * TT;
    const float* qp  = g_qkv + base + (size_t)tblk * 64;
    const float* kp0 = g_qkv + base + (size_t)64 * TT;

    #pragma unroll
    for (int f = tid; f < 1024; f += 256) {
        const int c = f >> 4, t4 = (f & 15) << 2;
        float4 v = *(const float4*)(qp + (size_t)c * TT + t4);
        float* d = Qs + c * SW + t4;
        d[0] = v.x * 0.125f; d[1] = v.y * 0.125f;
        d[2] = v.z * 0.125f; d[3] = v.w * 0.125f;
    }

    float m_i[4], l_i[4], O[4][4];
    #pragma unroll
    for (int i = 0; i < 4; i++) {
        m_i[i] = -1e30f; l_i[i] = 0.f;
        #pragma unroll
        for (int j = 0; j < 4; j++) O[i][j] = 0.f;
    }

    for (int sb = 0; sb < 16; sb++) {
        __syncthreads();
        const float* kp = kp0 + sb * 64;
        #pragma unroll
        for (int f = tid; f < 1024; f += 256) {
            const int c = f >> 4, s4 = (f & 15) << 2;
            float4 kv = *(const float4*)(kp + (size_t)c * TT + s4);
            float4 vv = *(const float4*)(kp + (size_t)(64 + c) * TT + s4);
            float* kd = Ks + c * SW + s4;
            kd[0] = kv.x; kd[1] = kv.y; kd[2] = kv.z; kd[3] = kv.w;
            float* vd = Vs + c * SW + s4;
            vd[0] = vv.x; vd[1] = vv.y; vd[2] = vv.z; vd[3] = vv.w;
        }
        __syncthreads();

        float S[4][4];
        #pragma unroll
        for (int i = 0; i < 4; i++)
            #pragma unroll
            for (int j = 0; j < 4; j++) S[i][j] = 0.f;

        #pragma unroll 16
        for (int c = 0; c < 64; c++) {
            float4 qa = *(const float4*)(Qs + c * SW + ty * 4);
            float4 ka = *(const float4*)(Ks + c * SW + tx * 4);
            float qr[4] = {qa.x, qa.y, qa.z, qa.w};
            float kr[4] = {ka.x, ka.y, ka.z, ka.w};
            #pragma unroll
            for (int i = 0; i < 4; i++)
                #pragma unroll
                for (int j = 0; j < 4; j++) S[i][j] = fmaf(qr[i], kr[j], S[i][j]);
        }

        #pragma unroll
        for (int i = 0; i < 4; i++) {
            float rm = fmaxf(fmaxf(S[i][0], S[i][1]), fmaxf(S[i][2], S[i][3]));
            rm = fmaxf(rm, __shfl_xor_sync(0xffffffffu, rm, 8));
            rm = fmaxf(rm, __shfl_xor_sync(0xffffffffu, rm, 4));
            rm = fmaxf(rm, __shfl_xor_sync(0xffffffffu, rm, 2));
            rm = fmaxf(rm, __shfl_xor_sync(0xffffffffu, rm, 1));
            const float mn   = fmaxf(m_i[i], rm);
            const float corr = __expf(m_i[i] - mn);
            m_i[i] = mn;
            float rs = 0.f;
            #pragma unroll
            for (int j = 0; j < 4; j++) { S[i][j] = __expf(S[i][j] - mn); rs += S[i][j]; }
            rs += __shfl_xor_sync(0xffffffffu, rs, 8);
            rs += __shfl_xor_sync(0xffffffffu, rs, 4);
            rs += __shfl_xor_sync(0xffffffffu, rs, 2);
            rs += __shfl_xor_sync(0xffffffffu, rs, 1);
            l_i[i] = l_i[i] * corr + rs;
            if (tx == 0) Cs[ty * 4 + i] = corr;
            #pragma unroll
            for (int j = 0; j < 4; j++)
                Ps[(tx * 4 + j) * SW + ty * 4 + i] = S[i][j];
        }
        __syncthreads();

        float4 cc = *(const float4*)(Cs + tx * 4);
        float cr[4] = {cc.x, cc.y, cc.z, cc.w};
        #pragma unroll
        for (int i = 0; i < 4; i++)
            #pragma unroll
            for (int j = 0; j < 4; j++) O[i][j] *= cr[j];

        #pragma unroll 16
        for (int s = 0; s < 64; s++) {
            float4 pb = *(const float4*)(Ps + s * SW + tx * 4);
            float pr[4] = {pb.x, pb.y, pb.z, pb.w};
            float vr[4];
            #pragma unroll
            for (int i = 0; i < 4; i++) vr[i] = Vs[(ty * 4 + i) * SW + s];
            #pragma unroll
            for (int i = 0; i < 4; i++)
                #pragma unroll
                for (int j = 0; j < 4; j++) O[i][j] = fmaf(vr[i], pr[j], O[i][j]);
        }
    }

    if (tx == 0) {
        #pragma unroll
        for (int i = 0; i < 4; i++) Ls[ty * 4 + i] = l_i[i];
    }
    __syncthreads();
    float4 lv = *(const float4*)(Ls + tx * 4);
    const float linv[4] = {1.f / lv.x, 1.f / lv.y, 1.f / lv.z, 1.f / lv.w};

    float* hp = g_h + ((size_t)b * CH + (size_t)head * 64) * TT + (size_t)tblk * 64;
    #pragma unroll
    for (int i = 0; i < 4; i++) {
        float4 v;
        v.x = O[i][0] * linv[0]; v.y = O[i][1] * linv[1];
        v.z = O[i][2] * linv[2]; v.w = O[i][3] * linv[3];
        *(float4*)(hp + (size_t)(ty * 4 + i) * TT + tx * 4) = v;
    }
}

// ---------------- launch ----------------------------------------------------
extern "C" void kernel_launch(void* const* d_in, const int* in_sizes, int n_in,
                              void* d_out, int out_size) {
    const float* x    = (const float*)d_in[0];
    const float* nw   = (const float*)d_in[1];
    const float* nb   = (const float*)d_in[2];
    const float* qkvw = (const float*)d_in[3];
    const float* qkvb = (const float*)d_in[4];
    const float* pw   = (const float*)d_in[5];
    const float* pb   = (const float*)d_in[6];
    float* out = (float*)d_out;

    const int attn_smem = (4 * 64 * SW + 128) * (int)sizeof(float);
    cudaFuncSetAttribute(attn_kernel, cudaFuncAttributeMaxDynamicSharedMemorySize,
                         attn_smem);

    gn_stats_kernel<<<BATCH * 32, 256>>>(x);
    mma_gemm_kernel<true, false><<<dim3(TT / 128, (3 * CH) / 128, BATCH), 256>>>(
        qkvw, x, qkvb, nw, nb, nullptr);
    attn_kernel<<<dim3(TT / 64, NHEAD, BATCH), 256, attn_smem>>>();
    mma_gemm_kernel<false, true><<<dim3(TT / 128, CH / 128, BATCH), 256>>>(
        pw, x, pb, nullptr, nullptr, out);
}

// round 7
// speedup vs baseline: 2.6185x; 2.3686x over previous
#include <cuda_runtime.h>
#include <cuda_fp16.h>
#include <stdint.h>
#include <math.h>

#define BATCH 16
#define CH    512
#define TT    1024
#define NHEAD 8
#define BHD   (BATCH * NHEAD)
#define HD    64

// ---------------- scratch ----------------------------------------------------
__device__ float g_mean[BATCH * 32];
__device__ float g_rstd[BATCH * 32];
__device__ float g_qkv[(size_t)BATCH * 3 * CH * TT];
__device__ __half g_Xh[(size_t)BATCH * TT * CH], g_Xl[(size_t)BATCH * TT * CH];
__device__ __half g_Whq[3 * CH * CH], g_Wlq[3 * CH * CH];
__device__ __half g_Whp[CH * CH],     g_Wlp[CH * CH];
__device__ __half g_Qh[(size_t)BHD * TT * HD], g_Ql[(size_t)BHD * TT * HD];
__device__ __half g_Kh[(size_t)BHD * TT * HD], g_Kl[(size_t)BHD * TT * HD];
__device__ __half g_Vh[(size_t)BHD * HD * TT], g_Vl[(size_t)BHD * HD * TT];
__device__ __half g_hh[(size_t)BATCH * TT * CH], g_hl[(size_t)BATCH * TT * CH];

// ---------------- helpers ------------------------------------------------------
__device__ __forceinline__ void split2(float a, float b, uint32_t& hi, uint32_t& lo) {
    __half2 h = __floats2half2_rn(a, b);
    float2 hf = __half22float2(h);
    __half2 l = __floats2half2_rn(a - hf.x, b - hf.y);
    hi = *reinterpret_cast<uint32_t*>(&h);
    lo = *reinterpret_cast<uint32_t*>(&l);
}
__device__ __forceinline__ void mma16816(float c[4], const uint32_t a[4],
                                         const uint32_t b[2]) {
    asm volatile(
        "mma.sync.aligned.m16n8k16.row.col.f32.f16.f16.f32 "
        "{%0,%1,%2,%3}, {%4,%5,%6,%7}, {%8,%9}, {%0,%1,%2,%3};"
        : "+f"(c[0]), "+f"(c[1]), "+f"(c[2]), "+f"(c[3])
        : "r"(a[0]), "r"(a[1]), "r"(a[2]), "r"(a[3]), "r"(b[0]), "r"(b[1]));
}
__device__ __forceinline__ uint32_t smem_u32(const void* p) {
    uint32_t a;
    asm("{ .reg .u64 t; cvta.to.shared.u64 t, %1; cvt.u32.u64 %0, t; }"
        : "=r"(a) : "l"(p));
    return a;
}
__device__ __forceinline__ uint32_t lds32(uint32_t a) {
    uint32_t v;
    asm volatile("ld.shared.b32 %0, [%1];" : "=r"(v) : "r"(a));
    return v;
}
__device__ __forceinline__ void cp16(uint32_t d, const void* s) {
    asm volatile("cp.async.cg.shared.global [%0], [%1], 16;" :: "r"(d), "l"(s));
}
#define CP_COMMIT() asm volatile("cp.async.commit_group;" ::: "memory")
#define CP_WAIT(n)  asm volatile("cp.async.wait_group %0;" :: "n"(n) : "memory")

// ---------------- GroupNorm statistics -----------------------------------------
__global__ void gn_stats_kernel(const float* __restrict__ x) {
    const int bg = blockIdx.x;
    const float4* base = (const float4*)(x + (size_t)bg * 16 * TT);
    float s = 0.f, ss = 0.f;
    for (int i = threadIdx.x; i < 4096; i += 256) {
        float4 v = base[i];
        s  += v.x + v.y + v.z + v.w;
        ss += v.x*v.x + v.y*v.y + v.z*v.z + v.w*v.w;
    }
    #pragma unroll
    for (int o = 16; o; o >>= 1) {
        s  += __shfl_down_sync(0xffffffffu, s,  o);
        ss += __shfl_down_sync(0xffffffffu, ss, o);
    }
    __shared__ float sh[16];
    const int w = threadIdx.x >> 5, l = threadIdx.x & 31;
    if (l == 0) { sh[w] = s; sh[8 + w] = ss; }
    __syncthreads();
    if (threadIdx.x == 0) {
        float S = 0.f, SS = 0.f;
        #pragma unroll
        for (int i = 0; i < 8; i++) { S += sh[i]; SS += sh[8 + i]; }
        const float mean = S * (1.f / 16384.f);
        const float var  = SS * (1.f / 16384.f) - mean * mean;
        g_mean[bg] = mean;
        g_rstd[bg] = rsqrtf(var + 1e-5f);
    }
}

// ---------------- weight pack ----------------------------------------------------
__global__ void w_pack_kernel(const float* __restrict__ qw,
                              const float* __restrict__ pw) {
    const int i = blockIdx.x * 256 + threadIdx.x;
    const int NQ = 3 * CH * CH / 2;
    uint32_t h, l;
    if (i < NQ) {
        float2 v = ((const float2*)qw)[i];
        split2(v.x, v.y, h, l);
        ((uint32_t*)g_Whq)[i] = h;
        ((uint32_t*)g_Wlq)[i] = l;
    } else {
        const int j = i - NQ;
        float2 v = ((const float2*)pw)[j];
        split2(v.x, v.y, h, l);
        ((uint32_t*)g_Whp)[j] = h;
        ((uint32_t*)g_Wlp)[j] = l;
    }
}

// ---------------- x pack: GroupNorm + split + transpose -> [b][t][c] ------------
__global__ void x_pack_kernel(const float* __restrict__ x,
                              const float* __restrict__ nw,
                              const float* __restrict__ nb) {
    __shared__ float tile[64][68];
    const int t0 = blockIdx.x * 64, c0 = blockIdx.y * 64, b = blockIdx.z;
    const int tid = threadIdx.x;
    const float* xb = x + (size_t)b * CH * TT;
    #pragma unroll
    for (int it = 0; it < 4; ++it) {
        const int f = tid + it * 256;
        const int cl = f >> 4, t4 = (f & 15) << 2;
        const int c = c0 + cl;
        float4 v = *(const float4*)(xb + (size_t)c * TT + t0 + t4);
        const int bg = (b << 5) + (c >> 4);
        const float w  = nw[c] * g_rstd[bg];
        const float bb = fmaf(-g_mean[bg], w, nb[c]);
        tile[cl][t4 + 0] = fmaf(v.x, w, bb);
        tile[cl][t4 + 1] = fmaf(v.y, w, bb);
        tile[cl][t4 + 2] = fmaf(v.z, w, bb);
        tile[cl][t4 + 3] = fmaf(v.w, w, bb);
    }
    __syncthreads();
    #pragma unroll
    for (int it = 0; it < 4; ++it) {
        const int f = tid + it * 256;
        const int tl = f >> 4, c4 = (f & 15) << 2;
        uint32_t h0, l0, h1, l1;
        split2(tile[c4 + 0][tl], tile[c4 + 1][tl], h0, l0);
        split2(tile[c4 + 2][tl], tile[c4 + 3][tl], h1, l1);
        const size_t off = ((size_t)b * TT + t0 + tl) * CH + c0 + c4;
        *(uint2*)(g_Xh + off) = make_uint2(h0, h1);
        *(uint2*)(g_Xl + off) = make_uint2(l0, l1);
    }
}

// ---------------- qkv pack: q,k -> [bh][t][c] (q*0.125), v -> [bh][c][s] ---------
__global__ void qkv_pack_kernel() {
    const int mode = blockIdx.z, bh = blockIdx.y, t0 = blockIdx.x * 64;
    const int b = bh >> 3, head = bh & 7;
    const int tid = threadIdx.x;
    const float* src = g_qkv + ((size_t)b * 3 * CH + head * 192 + mode * 64) * TT;
    if (mode == 2) {
        #pragma unroll
        for (int it = 0; it < 4; ++it) {
            const int f = tid + it * 256;
            const int c = f >> 4, s4 = (f & 15) << 2;
            float4 v = *(const float4*)(src + (size_t)c * TT + t0 + s4);
            uint32_t h0, l0, h1, l1;
            split2(v.x, v.y, h0, l0);
            split2(v.z, v.w, h1, l1);
            const size_t off = ((size_t)bh * HD + c) * TT + t0 + s4;
            *(uint2*)(g_Vh + off) = make_uint2(h0, h1);
            *(uint2*)(g_Vl + off) = make_uint2(l0, l1);
        }
    } else {
        __shared__ float tile[64][68];
        const float scale = (mode == 0) ? 0.125f : 1.0f;
        #pragma unroll
        for (int it = 0; it < 4; ++it) {
            const int f = tid + it * 256;
            const int c = f >> 4, t4 = (f & 15) << 2;
            float4 v = *(const float4*)(src + (size_t)c * TT + t0 + t4);
            tile[c][t4 + 0] = v.x * scale;
            tile[c][t4 + 1] = v.y * scale;
            tile[c][t4 + 2] = v.z * scale;
            tile[c][t4 + 3] = v.w * scale;
        }
        __syncthreads();
        __half* dh = (mode == 0) ? g_Qh : g_Kh;
        __half* dl = (mode == 0) ? g_Ql : g_Kl;
        #pragma unroll
        for (int it = 0; it < 4; ++it) {
            const int f = tid + it * 256;
            const int tl = f >> 4, c4 = (f & 15) << 2;
            uint32_t h0, l0, h1, l1;
            split2(tile[c4 + 0][tl], tile[c4 + 1][tl], h0, l0);
            split2(tile[c4 + 2][tl], tile[c4 + 3][tl], h1, l1);
            const size_t off = ((size_t)bh * TT + t0 + tl) * HD + c4;
            *(uint2*)(dh + off) = make_uint2(h0, h1);
            *(uint2*)(dl + off) = make_uint2(l0, l1);
        }
    }
}

// ---------------- HMMA GEMM: pure fp16 cp.async pipeline ------------------------
#define GP 40
#define GSB (128 * GP)
#define GEMM_SMEM (2 * 4 * GSB * 2)

template<bool IS_PROJ>
__global__ __launch_bounds__(256, 2)
void hgemm_kernel(const float* __restrict__ bias,
                  const float* __restrict__ resid,
                  float* __restrict__ outp) {
    extern __shared__ __half smh[];
    const uint32_t sb = smem_u32(smh);
    const int tid = threadIdx.x, lane = tid & 31, wid = tid >> 5;
    const int g = lane >> 2, tig = lane & 3;
    const int b = blockIdx.z, m0 = blockIdx.y * 128, n0 = blockIdx.x * 128;
    const int warp_m = wid >> 2, warp_n = wid & 3;

    const __half* Ahg = IS_PROJ ? g_Whp : g_Whq;
    const __half* Alg = IS_PROJ ? g_Wlp : g_Wlq;
    const __half* Bhg = (IS_PROJ ? g_hh : g_Xh) + (size_t)b * TT * CH;
    const __half* Blg = (IS_PROJ ? g_hl : g_Xl) + (size_t)b * TT * CH;
    float* Ob = IS_PROJ ? (outp + (size_t)b * CH * TT)
                        : (g_qkv + (size_t)b * 3 * CH * TT);

    float acc[4][4][4];
    #pragma unroll
    for (int mi = 0; mi < 4; ++mi)
        #pragma unroll
        for (int ni = 0; ni < 4; ++ni)
            #pragma unroll
            for (int r = 0; r < 4; ++r) acc[mi][ni][r] = 0.f;

    auto issue = [&](int ck) {
        const uint32_t st = sb + (ck & 1) * (4 * GSB * 2);
        const int k0 = ck * 32;
        #pragma unroll
        for (int it = 0; it < 2; ++it) {
            const int f = tid + it * 256;
            const int row = f >> 2, sg = (f & 3) << 3;
            const uint32_t da = st + (row * GP + sg) * 2;
            cp16(da,           Ahg + (size_t)(m0 + row) * CH + k0 + sg);
            cp16(da + GSB * 2, Alg + (size_t)(m0 + row) * CH + k0 + sg);
            const uint32_t db = da + 2 * GSB * 2;
            cp16(db,           Bhg + (size_t)(n0 + row) * CH + k0 + sg);
            cp16(db + GSB * 2, Blg + (size_t)(n0 + row) * CH + k0 + sg);
        }
    };

    auto compute = [&](int ck) {
        const uint32_t st = sb + (ck & 1) * (4 * GSB * 2);
        const uint32_t aH = st, aL = st + GSB * 2;
        const uint32_t bH = st + 2 * GSB * 2, bL = st + 3 * GSB * 2;
        #pragma unroll
        for (int kk = 0; kk < 32; kk += 16) {
            uint32_t afh[4][4], afl[4][4];
            #pragma unroll
            for (int mi = 0; mi < 4; ++mi) {
                const uint32_t a = ((warp_m * 64 + mi * 16 + g) * GP + kk + tig * 2) * 2;
                afh[mi][0] = lds32(aH + a);
                afh[mi][1] = lds32(aH + a + 8 * GP * 2);
                afh[mi][2] = lds32(aH + a + 16);
                afh[mi][3] = lds32(aH + a + 8 * GP * 2 + 16);
                afl[mi][0] = lds32(aL + a);
                afl[mi][1] = lds32(aL + a + 8 * GP * 2);
                afl[mi][2] = lds32(aL + a + 16);
                afl[mi][3] = lds32(aL + a + 8 * GP * 2 + 16);
            }
            #pragma unroll
            for (int ni = 0; ni < 4; ++ni) {
                const uint32_t bo = ((warp_n * 32 + ni * 8 + g) * GP + kk + tig * 2) * 2;
                uint32_t bfh[2], bfl[2];
                bfh[0] = lds32(bH + bo); bfh[1] = lds32(bH + bo + 16);
                bfl[0] = lds32(bL + bo); bfl[1] = lds32(bL + bo + 16);
                #pragma unroll
                for (int mi = 0; mi < 4; ++mi) {
                    mma16816(acc[mi][ni], afh[mi], bfh);
                    mma16816(acc[mi][ni], afl[mi], bfh);
                    mma16816(acc[mi][ni], afh[mi], bfl);
                }
            }
        }
    };

    issue(0); CP_COMMIT();
    for (int ck = 0; ck < 16; ++ck) {
        if (ck < 15) { issue(ck + 1); CP_COMMIT(); CP_WAIT(1); }
        else         { CP_WAIT(0); }
        __syncthreads();
        compute(ck);
        __syncthreads();
    }

    const int mbase = m0 + warp_m * 64;
    const int nbase = n0 + warp_n * 32;
    const float* xres = IS_PROJ ? (resid + (size_t)b * CH * TT) : nullptr;
    #pragma unroll
    for (int mi = 0; mi < 4; ++mi) {
        const int mA = mbase + mi * 16 + g;
        const int mB = mA + 8;
        const float biA = bias[mA], biB = bias[mB];
        #pragma unroll
        for (int ni = 0; ni < 4; ++ni) {
            const int t = nbase + ni * 8 + tig * 2;
            float2 v0, v1;
            v0.x = acc[mi][ni][0] + biA; v0.y = acc[mi][ni][1] + biA;
            v1.x = acc[mi][ni][2] + biB; v1.y = acc[mi][ni][3] + biB;
            if (IS_PROJ) {
                float2 r0 = *(const float2*)(xres + (size_t)mA * TT + t);
                float2 r1 = *(const float2*)(xres + (size_t)mB * TT + t);
                v0.x += r0.x; v0.y += r0.y;
                v1.x += r1.x; v1.y += r1.y;
            }
            *(float2*)(Ob + (size_t)mA * TT + t) = v0;
            *(float2*)(Ob + (size_t)mB * TT + t) = v1;
        }
    }
}

// ---------------- HMMA flash attention ------------------------------------------
// smem (halves): Qh 0, Ql 9216; stage s at 18432+s*18432: Kh +0, Kl +4608,
//                Vh +9216, Vl +13824. Pitch 72 halves.
#define AP 72
#define ATTN_SMEM ((18432 + 2 * 18432) * 2)

__global__ __launch_bounds__(256)
void attn_kernel() {
    extern __shared__ __half sa[];
    const uint32_t sb = smem_u32(sa);
    const int tid = threadIdx.x, lane = tid & 31, wid = tid >> 5;
    const int g = lane >> 2, tig = lane & 3;
    const int tblk = blockIdx.x, head = blockIdx.y, b = blockIdx.z;
    const int bh = b * NHEAD + head;
    const int t0 = tblk * 128;

    {
        const __half* qh = g_Qh + ((size_t)bh * TT + t0) * HD;
        const __half* ql = g_Ql + ((size_t)bh * TT + t0) * HD;
        #pragma unroll
        for (int it = 0; it < 4; ++it) {
            const int f = tid + it * 256;
            const int row = f >> 3, sg = (f & 7) << 3;
            const uint32_t d = sb + (row * AP + sg) * 2;
            cp16(d,            qh + row * HD + sg);
            cp16(d + 9216 * 2, ql + row * HD + sg);
        }
    }
    // FIXED (R6 NaN bug): full 64x64 tile coverage — 512 cp16 per array.
    auto issueKV = [&](int kb) {
        const uint32_t st = sb + (18432 + (kb & 1) * 18432) * 2;
        const int s0 = kb * 64;
        const __half* kh = g_Kh + ((size_t)bh * TT + s0) * HD;
        const __half* kl = g_Kl + ((size_t)bh * TT + s0) * HD;
        const __half* vh = g_Vh + (size_t)bh * HD * TT + s0;
        const __half* vl = g_Vl + (size_t)bh * HD * TT + s0;
        #pragma unroll
        for (int it = 0; it < 2; ++it) {
            const int f = tid + it * 256;
            const int row = f >> 3, sg = (f & 7) << 3;   // row 0..63, sg 0..56
            const uint32_t dk = st + (row * AP + sg) * 2;
            cp16(dk,            kh + (size_t)row * HD + sg);
            cp16(dk + 4608 * 2, kl + (size_t)row * HD + sg);
            const uint32_t dv = st + (9216 + row * AP + sg) * 2;
            cp16(dv,            vh + (size_t)row * TT + sg);
            cp16(dv + 4608 * 2, vl + (size_t)row * TT + sg);
        }
    };

    issueKV(0); CP_COMMIT();

    float m_i0 = -1e30f, m_i1 = -1e30f, l_i0 = 0.f, l_i1 = 0.f;
    float oacc[8][4];
    #pragma unroll
    for (int nc = 0; nc < 8; ++nc)
        #pragma unroll
        for (int r = 0; r < 4; ++r) oacc[nc][r] = 0.f;

    for (int kb = 0; kb < 16; ++kb) {
        if (kb < 15) { issueKV(kb + 1); CP_COMMIT(); CP_WAIT(1); }
        else         { CP_WAIT(0); }
        __syncthreads();
        const uint32_t st = sb + (18432 + (kb & 1) * 18432) * 2;

        // ---- S = Q K^T (3-term split)
        float sacc[8][4];
        #pragma unroll
        for (int ni = 0; ni < 8; ++ni)
            #pragma unroll
            for (int r = 0; r < 4; ++r) sacc[ni][r] = 0.f;

        #pragma unroll
        for (int ks = 0; ks < 4; ++ks) {
            const uint32_t qa = sb + ((wid * 16 + g) * AP + ks * 16 + tig * 2) * 2;
            uint32_t ah[4], al[4];
            ah[0] = lds32(qa);
            ah[1] = lds32(qa + 8 * AP * 2);
            ah[2] = lds32(qa + 16);
            ah[3] = lds32(qa + 8 * AP * 2 + 16);
            al[0] = lds32(qa + 9216 * 2);
            al[1] = lds32(qa + 9216 * 2 + 8 * AP * 2);
            al[2] = lds32(qa + 9216 * 2 + 16);
            al[3] = lds32(qa + 9216 * 2 + 8 * AP * 2 + 16);
            #pragma unroll
            for (int ni = 0; ni < 8; ++ni) {
                const uint32_t ka = st + ((ni * 8 + g) * AP + ks * 16 + tig * 2) * 2;
                uint32_t bh2[2], bl2[2];
                bh2[0] = lds32(ka);            bh2[1] = lds32(ka + 16);
                bl2[0] = lds32(ka + 4608 * 2); bl2[1] = lds32(ka + 4608 * 2 + 16);
                mma16816(sacc[ni], ah, bh2);
                mma16816(sacc[ni], al, bh2);
                mma16816(sacc[ni], ah, bl2);
            }
        }

        // ---- online softmax (rows g and g+8 within warp's 16-row band)
        float mx0 = -1e30f, mx1 = -1e30f;
        #pragma unroll
        for (int ni = 0; ni < 8; ++ni) {
            mx0 = fmaxf(mx0, fmaxf(sacc[ni][0], sacc[ni][1]));
            mx1 = fmaxf(mx1, fmaxf(sacc[ni][2], sacc[ni][3]));
        }
        mx0 = fmaxf(mx0, __shfl_xor_sync(0xffffffffu, mx0, 1));
        mx0 = fmaxf(mx0, __shfl_xor_sync(0xffffffffu, mx0, 2));
        mx1 = fmaxf(mx1, __shfl_xor_sync(0xffffffffu, mx1, 1));
        mx1 = fmaxf(mx1, __shfl_xor_sync(0xffffffffu, mx1, 2));
        const float mn0 = fmaxf(m_i0, mx0), mn1 = fmaxf(m_i1, mx1);
        const float c0 = __expf(m_i0 - mn0), c1 = __expf(m_i1 - mn1);
        m_i0 = mn0; m_i1 = mn1;
        float rs0 = 0.f, rs1 = 0.f;
        uint32_t pfrag[8][2];
        #pragma unroll
        for (int ni = 0; ni < 8; ++ni) {
            const float p0 = __expf(sacc[ni][0] - mn0);
            const float p1 = __expf(sacc[ni][1] - mn0);
            const float p2 = __expf(sacc[ni][2] - mn1);
            const float p3 = __expf(sacc[ni][3] - mn1);
            rs0 += p0 + p1; rs1 += p2 + p3;
            __half2 h0 = __floats2half2_rn(p0, p1);
            __half2 h1 = __floats2half2_rn(p2, p3);
            pfrag[ni][0] = *reinterpret_cast<uint32_t*>(&h0);
            pfrag[ni][1] = *reinterpret_cast<uint32_t*>(&h1);
        }
        rs0 += __shfl_xor_sync(0xffffffffu, rs0, 1);
        rs0 += __shfl_xor_sync(0xffffffffu, rs0, 2);
        rs1 += __shfl_xor_sync(0xffffffffu, rs1, 1);
        rs1 += __shfl_xor_sync(0xffffffffu, rs1, 2);
        l_i0 = l_i0 * c0 + rs0;
        l_i1 = l_i1 * c1 + rs1;
        #pragma unroll
        for (int nc = 0; nc < 8; ++nc) {
            oacc[nc][0] *= c0; oacc[nc][1] *= c0;
            oacc[nc][2] *= c1; oacc[nc][3] *= c1;
        }

        // ---- O += P V^T (P fp16, V split 2-term)
        #pragma unroll
        for (int ks = 0; ks < 4; ++ks) {
            const uint32_t pa[4] = { pfrag[2 * ks][0], pfrag[2 * ks][1],
                                     pfrag[2 * ks + 1][0], pfrag[2 * ks + 1][1] };
            #pragma unroll
            for (int nc = 0; nc < 8; ++nc) {
                const uint32_t va = st + (9216 + (nc * 8 + g) * AP + ks * 16 + tig * 2) * 2;
                uint32_t vh2[2], vl2[2];
                vh2[0] = lds32(va);            vh2[1] = lds32(va + 16);
                vl2[0] = lds32(va + 4608 * 2); vl2[1] = lds32(va + 4608 * 2 + 16);
                mma16816(oacc[nc], pa, vh2);
                mma16816(oacc[nc], pa, vl2);
            }
        }
        __syncthreads();
    }

    // ---- epilogue: O/l split to fp16, store [b][t][c]
    const float inv0 = 1.f / l_i0, inv1 = 1.f / l_i1;
    #pragma unroll
    for (int nc = 0; nc < 8; ++nc) {
        uint32_t h, l;
        const size_t off0 = ((size_t)b * TT + t0 + wid * 16 + g) * CH
                          + head * 64 + nc * 8 + tig * 2;
        split2(oacc[nc][0] * inv0, oacc[nc][1] * inv0, h, l);
        *(uint32_t*)(g_hh + off0) = h;
        *(uint32_t*)(g_hl + off0) = l;
        const size_t off1 = off0 + (size_t)8 * CH;
        split2(oacc[nc][2] * inv1, oacc[nc][3] * inv1, h, l);
        *(uint32_t*)(g_hh + off1) = h;
        *(uint32_t*)(g_hl + off1) = l;
    }
}

// ---------------- launch ----------------------------------------------------------
extern "C" void kernel_launch(void* const* d_in, const int* in_sizes, int n_in,
                              void* d_out, int out_size) {
    const float* x    = (const float*)d_in[0];
    const float* nw   = (const float*)d_in[1];
    const float* nb   = (const float*)d_in[2];
    const float* qkvw = (const float*)d_in[3];
    const float* qkvb = (const float*)d_in[4];
    const float* pw   = (const float*)d_in[5];
    const float* pb   = (const float*)d_in[6];
    float* out = (float*)d_out;

    cudaFuncSetAttribute(hgemm_kernel<false>,
                         cudaFuncAttributeMaxDynamicSharedMemorySize, GEMM_SMEM);
    cudaFuncSetAttribute(hgemm_kernel<true>,
                         cudaFuncAttributeMaxDynamicSharedMemorySize, GEMM_SMEM);
    cudaFuncSetAttribute(attn_kernel,
                         cudaFuncAttributeMaxDynamicSharedMemorySize, ATTN_SMEM);

    gn_stats_kernel<<<BATCH * 32, 256>>>(x);
    w_pack_kernel<<<(3 * CH * CH + CH * CH) / 2 / 256, 256>>>(qkvw, pw);
    x_pack_kernel<<<dim3(16, 8, 16), 256>>>(x, nw, nb);
    hgemm_kernel<false><<<dim3(8, 12, BATCH), 256, GEMM_SMEM>>>(qkvb, nullptr, nullptr);
    qkv_pack_kernel<<<dim3(16, BHD, 3), 256>>>();
    attn_kernel<<<dim3(8, NHEAD, BATCH), 256, ATTN_SMEM>>>();
    hgemm_kernel<true><<<dim3(8, 4, BATCH), 256, GEMM_SMEM>>>(pb, x, out);
}

// round 8
// speedup vs baseline: 3.3939x; 1.2961x over previous
#include <cuda_runtime.h>
#include <cuda_fp16.h>
#include <stdint.h>
#include <math.h>

#define BATCH 16
#define CH    512
#define TT    1024
#define NHEAD 8
#define BHD   (BATCH * NHEAD)
#define HD    64

// ---------------- scratch ----------------------------------------------------
__device__ float g_mean[BATCH * 32];
__device__ float g_rstd[BATCH * 32];
__device__ __half g_Xh[(size_t)BATCH * TT * CH], g_Xl[(size_t)BATCH * TT * CH];
__device__ __half g_Whq[3 * CH * CH], g_Wlq[3 * CH * CH];
__device__ __half g_Whp[CH * CH],     g_Wlp[CH * CH];
__device__ __half g_Qh[(size_t)BHD * TT * HD], g_Ql[(size_t)BHD * TT * HD];
__device__ __half g_Kh[(size_t)BHD * TT * HD];
__device__ __half g_Vh[(size_t)BHD * HD * TT];
__device__ __half g_hh[(size_t)BATCH * TT * CH], g_hl[(size_t)BATCH * TT * CH];

// ---------------- helpers ------------------------------------------------------
__device__ __forceinline__ void split2(float a, float b, uint32_t& hi, uint32_t& lo) {
    __half2 h = __floats2half2_rn(a, b);
    float2 hf = __half22float2(h);
    __half2 l = __floats2half2_rn(a - hf.x, b - hf.y);
    hi = *reinterpret_cast<uint32_t*>(&h);
    lo = *reinterpret_cast<uint32_t*>(&l);
}
__device__ __forceinline__ void mma16816(float c[4], const uint32_t a[4],
                                         uint32_t b0, uint32_t b1) {
    asm volatile(
        "mma.sync.aligned.m16n8k16.row.col.f32.f16.f16.f32 "
        "{%0,%1,%2,%3}, {%4,%5,%6,%7}, {%8,%9}, {%0,%1,%2,%3};"
        : "+f"(c[0]), "+f"(c[1]), "+f"(c[2]), "+f"(c[3])
        : "r"(a[0]), "r"(a[1]), "r"(a[2]), "r"(a[3]), "r"(b0), "r"(b1));
}
__device__ __forceinline__ void ldsm4(uint32_t r[4], uint32_t addr) {
    asm volatile("ldmatrix.sync.aligned.m8n8.x4.shared.b16 {%0,%1,%2,%3}, [%4];"
                 : "=r"(r[0]), "=r"(r[1]), "=r"(r[2]), "=r"(r[3]) : "r"(addr));
}
__device__ __forceinline__ uint32_t smem_u32(const void* p) {
    uint32_t a;
    asm("{ .reg .u64 t; cvta.to.shared.u64 t, %1; cvt.u32.u64 %0, t; }"
        : "=r"(a) : "l"(p));
    return a;
}
__device__ __forceinline__ void cp16(uint32_t d, const void* s) {
    asm volatile("cp.async.cg.shared.global [%0], [%1], 16;" :: "r"(d), "l"(s));
}
#define CP_COMMIT() asm volatile("cp.async.commit_group;" ::: "memory")
#define CP_WAIT(n)  asm volatile("cp.async.wait_group %0;" :: "n"(n) : "memory")

// ---------------- GroupNorm statistics -----------------------------------------
__global__ void gn_stats_kernel(const float* __restrict__ x) {
    const int bg = blockIdx.x;
    const float4* base = (const float4*)(x + (size_t)bg * 16 * TT);
    float s = 0.f, ss = 0.f;
    for (int i = threadIdx.x; i < 4096; i += 256) {
        float4 v = base[i];
        s  += v.x + v.y + v.z + v.w;
        ss += v.x*v.x + v.y*v.y + v.z*v.z + v.w*v.w;
    }
    #pragma unroll
    for (int o = 16; o; o >>= 1) {
        s  += __shfl_down_sync(0xffffffffu, s,  o);
        ss += __shfl_down_sync(0xffffffffu, ss, o);
    }
    __shared__ float sh[16];
    const int w = threadIdx.x >> 5, l = threadIdx.x & 31;
    if (l == 0) { sh[w] = s; sh[8 + w] = ss; }
    __syncthreads();
    if (threadIdx.x == 0) {
        float S = 0.f, SS = 0.f;
        #pragma unroll
        for (int i = 0; i < 8; i++) { S += sh[i]; SS += sh[8 + i]; }
        const float mean = S * (1.f / 16384.f);
        const float var  = SS * (1.f / 16384.f) - mean * mean;
        g_mean[bg] = mean;
        g_rstd[bg] = rsqrtf(var + 1e-5f);
    }
}

// ---------------- weight pack ----------------------------------------------------
__global__ void w_pack_kernel(const float* __restrict__ qw,
                              const float* __restrict__ pw) {
    const int i = blockIdx.x * 256 + threadIdx.x;
    const int NQ = 3 * CH * CH / 2;
    uint32_t h, l;
    if (i < NQ) {
        float2 v = ((const float2*)qw)[i];
        split2(v.x, v.y, h, l);
        ((uint32_t*)g_Whq)[i] = h;
        ((uint32_t*)g_Wlq)[i] = l;
    } else {
        const int j = i - NQ;
        float2 v = ((const float2*)pw)[j];
        split2(v.x, v.y, h, l);
        ((uint32_t*)g_Whp)[j] = h;
        ((uint32_t*)g_Wlp)[j] = l;
    }
}

// ---------------- x pack: GroupNorm + split + transpose -> [b][t][c] ------------
__global__ void x_pack_kernel(const float* __restrict__ x,
                              const float* __restrict__ nw,
                              const float* __restrict__ nb) {
    __shared__ float tile[64][68];
    const int t0 = blockIdx.x * 64, c0 = blockIdx.y * 64, b = blockIdx.z;
    const int tid = threadIdx.x;
    const float* xb = x + (size_t)b * CH * TT;
    #pragma unroll
    for (int it = 0; it < 4; ++it) {
        const int f = tid + it * 256;
        const int cl = f >> 4, t4 = (f & 15) << 2;
        const int c = c0 + cl;
        float4 v = *(const float4*)(xb + (size_t)c * TT + t0 + t4);
        const int bg = (b << 5) + (c >> 4);
        const float w  = nw[c] * g_rstd[bg];
        const float bb = fmaf(-g_mean[bg], w, nb[c]);
        tile[cl][t4 + 0] = fmaf(v.x, w, bb);
        tile[cl][t4 + 1] = fmaf(v.y, w, bb);
        tile[cl][t4 + 2] = fmaf(v.z, w, bb);
        tile[cl][t4 + 3] = fmaf(v.w, w, bb);
    }
    __syncthreads();
    #pragma unroll
    for (int it = 0; it < 4; ++it) {
        const int f = tid + it * 256;
        const int tl = f >> 4, c4 = (f & 15) << 2;
        uint32_t h0, l0, h1, l1;
        split2(tile[c4 + 0][tl], tile[c4 + 1][tl], h0, l0);
        split2(tile[c4 + 2][tl], tile[c4 + 3][tl], h1, l1);
        const size_t off = ((size_t)b * TT + t0 + tl) * CH + c0 + c4;
        *(uint2*)(g_Xh + off) = make_uint2(h0, h1);
        *(uint2*)(g_Xl + off) = make_uint2(l0, l1);
    }
}

// ---------------- HMMA GEMM (split-fp16 3-term), ldmatrix fragments -------------
// qkv (IS_PROJ=0): A = gn(x) rows t, B = Wq rows m; frag = [t][m];
//                  epilogue packs Q/K/V split-fp16 directly.
// proj (IS_PROJ=1): A = Wp rows m, B = h rows t; frag = [m][t]; fp32 out + resid.
#define GP 40
#define GSB (128 * GP)
#define GEMM_SMEM (2 * 4 * GSB * 2)

template<bool IS_PROJ>
__global__ __launch_bounds__(256, 2)
void hgemm_kernel(const float* __restrict__ bias,
                  const float* __restrict__ resid,
                  float* __restrict__ outp) {
    extern __shared__ __half smh[];
    const uint32_t sb = smem_u32(smh);
    const int tid = threadIdx.x, lane = tid & 31, wid = tid >> 5;
    const int g = lane >> 2, tig = lane & 3;
    const int b = blockIdx.z;
    const int r0 = (IS_PROJ ? blockIdx.y : blockIdx.x) * 128;  // A-row base
    const int c0 = (IS_PROJ ? blockIdx.x : blockIdx.y) * 128;  // B-row base
    const int warp_m = wid >> 2, warp_n = wid & 3;

    const __half *pAh, *pAl, *pBh, *pBl;
    if (IS_PROJ) {
        pAh = g_Whp + (size_t)r0 * CH;            pAl = g_Wlp + (size_t)r0 * CH;
        pBh = g_hh + ((size_t)b * TT + c0) * CH;  pBl = g_hl + ((size_t)b * TT + c0) * CH;
    } else {
        pAh = g_Xh + ((size_t)b * TT + r0) * CH;  pAl = g_Xl + ((size_t)b * TT + r0) * CH;
        pBh = g_Whq + (size_t)c0 * CH;            pBl = g_Wlq + (size_t)c0 * CH;
    }

    float acc[4][4][4];
    #pragma unroll
    for (int mi = 0; mi < 4; ++mi)
        #pragma unroll
        for (int ni = 0; ni < 4; ++ni)
            #pragma unroll
            for (int r = 0; r < 4; ++r) acc[mi][ni][r] = 0.f;

    // ldmatrix per-lane row/k offsets
    const int aRow = warp_m * 64 + (lane & 15);
    const int aK   = (lane >> 4) << 3;
    const int bRow = warp_n * 32 + (lane & 7) + ((lane >> 4) << 3);
    const int bK   = ((lane >> 3) & 1) << 3;

    auto issue = [&](int ck) {
        const uint32_t st = sb + (ck & 1) * (4 * GSB * 2);
        const int k0 = ck * 32;
        #pragma unroll
        for (int it = 0; it < 2; ++it) {
            const int f = tid + it * 256;
            const int row = f >> 2, sg = (f & 3) << 3;
            const uint32_t da = st + (row * GP + sg) * 2;
            cp16(da,           pAh + (size_t)row * CH + k0 + sg);
            cp16(da + GSB * 2, pAl + (size_t)row * CH + k0 + sg);
            const uint32_t db = da + 2 * GSB * 2;
            cp16(db,           pBh + (size_t)row * CH + k0 + sg);
            cp16(db + GSB * 2, pBl + (size_t)row * CH + k0 + sg);
        }
    };

    auto compute = [&](int ck) {
        const uint32_t st = sb + (ck & 1) * (4 * GSB * 2);
        const uint32_t aH = st, aL = st + GSB * 2;
        const uint32_t bH = st + 2 * GSB * 2, bL = st + 3 * GSB * 2;
        #pragma unroll
        for (int kk = 0; kk < 32; kk += 16) {
            uint32_t afh[4][4], afl[4][4];
            #pragma unroll
            for (int mi = 0; mi < 4; ++mi) {
                const uint32_t ao = ((aRow + mi * 16) * GP + kk + aK) * 2;
                ldsm4(afh[mi], aH + ao);
                ldsm4(afl[mi], aL + ao);
            }
            #pragma unroll
            for (int nj = 0; nj < 2; ++nj) {
                const uint32_t bo = ((bRow + nj * 16) * GP + kk + bK) * 2;
                uint32_t bfh[4], bfl[4];
                ldsm4(bfh, bH + bo);
                ldsm4(bfl, bL + bo);
                #pragma unroll
                for (int mi = 0; mi < 4; ++mi) {
                    mma16816(acc[mi][nj * 2 + 0], afh[mi], bfh[0], bfh[1]);
                    mma16816(acc[mi][nj * 2 + 0], afl[mi], bfh[0], bfh[1]);
                    mma16816(acc[mi][nj * 2 + 0], afh[mi], bfl[0], bfl[1]);
                    mma16816(acc[mi][nj * 2 + 1], afh[mi], bfh[2], bfh[3]);
                    mma16816(acc[mi][nj * 2 + 1], afl[mi], bfh[2], bfh[3]);
                    mma16816(acc[mi][nj * 2 + 1], afh[mi], bfl[2], bfl[3]);
                }
            }
        }
    };

    issue(0); CP_COMMIT();
    for (int ck = 0; ck < 16; ++ck) {
        if (ck < 15) { issue(ck + 1); CP_COMMIT(); CP_WAIT(1); }
        else         { CP_WAIT(0); }
        __syncthreads();
        compute(ck);
        __syncthreads();
    }

    if (IS_PROJ) {
        // frag rows = m (out channel), cols = t
        const int mbase = r0 + warp_m * 64;
        const int nbase = c0 + warp_n * 32;
        const float* xres = resid + (size_t)b * CH * TT;
        float* ob = outp + (size_t)b * CH * TT;
        #pragma unroll
        for (int mi = 0; mi < 4; ++mi) {
            const int mA = mbase + mi * 16 + g;
            const int mB = mA + 8;
            const float biA = bias[mA], biB = bias[mB];
            #pragma unroll
            for (int ni = 0; ni < 4; ++ni) {
                const int t = nbase + ni * 8 + tig * 2;
                float2 v0, v1;
                v0.x = acc[mi][ni][0] + biA; v0.y = acc[mi][ni][1] + biA;
                v1.x = acc[mi][ni][2] + biB; v1.y = acc[mi][ni][3] + biB;
                float2 r0v = *(const float2*)(xres + (size_t)mA * TT + t);
                float2 r1v = *(const float2*)(xres + (size_t)mB * TT + t);
                v0.x += r0v.x; v0.y += r0v.y;
                v1.x += r1v.x; v1.y += r1v.y;
                *(float2*)(ob + (size_t)mA * TT + t) = v0;
                *(float2*)(ob + (size_t)mB * TT + t) = v1;
            }
        }
    } else {
        // frag rows = t, cols = m in [0, 1536); pack Q/K/V directly
        #pragma unroll
        for (int ni = 0; ni < 4; ++ni) {
            const int m = c0 + warp_n * 32 + ni * 8 + tig * 2;
            const int head = m / 192;
            const int rmod = m - head * 192;
            const int kind = rmod >> 6, c = rmod & 63;
            const int bh = b * NHEAD + head;
            const float b0v = bias[m], b1v = bias[m + 1];
            #pragma unroll
            for (int mi = 0; mi < 4; ++mi) {
                #pragma unroll
                for (int rr = 0; rr < 2; ++rr) {
                    const int t = r0 + warp_m * 64 + mi * 16 + g + rr * 8;
                    const float v0 = acc[mi][ni][rr * 2 + 0] + b0v;
                    const float v1 = acc[mi][ni][rr * 2 + 1] + b1v;
                    if (kind == 0) {
                        uint32_t h, l; split2(v0, v1, h, l);
                        const size_t off = ((size_t)bh * TT + t) * HD + c;
                        *(uint32_t*)(g_Qh + off) = h;
                        *(uint32_t*)(g_Ql + off) = l;
                    } else if (kind == 1) {
                        __half2 h2 = __floats2half2_rn(v0, v1);
                        *(__half2*)(g_Kh + ((size_t)bh * TT + t) * HD + c) = h2;
                    } else {
                        g_Vh[((size_t)bh * HD + c) * TT + t]       = __float2half_rn(v0);
                        g_Vh[((size_t)bh * HD + c + 1) * TT + t]   = __float2half_rn(v1);
                    }
                }
            }
        }
    }
}

// ---------------- HMMA flash attention (QK 2-term, PV 1-term) -------------------
// smem halves: Qh @0 (128x72), Ql @9216; stage k @18432+k*9216: Kh +0, Vh +4608.
#define AP 72
#define ATTN_SMEM ((18432 + 2 * 9216) * 2)   // 73728 bytes

__global__ __launch_bounds__(256)
void attn_kernel() {
    extern __shared__ __half sa[];
    const uint32_t sb = smem_u32(sa);
    const int tid = threadIdx.x, lane = tid & 31, wid = tid >> 5;
    const int g = lane >> 2, tig = lane & 3;
    const int tblk = blockIdx.x, head = blockIdx.y, b = blockIdx.z;
    const int bh = b * NHEAD + head;
    const int t0 = tblk * 128;

    {   // Q hi+lo: 128 rows x 64 halves each
        const __half* qh = g_Qh + ((size_t)bh * TT + t0) * HD;
        const __half* ql = g_Ql + ((size_t)bh * TT + t0) * HD;
        #pragma unroll
        for (int it = 0; it < 4; ++it) {
            const int f = tid + it * 256;
            const int row = f >> 3, sg = (f & 7) << 3;
            const uint32_t d = sb + (row * AP + sg) * 2;
            cp16(d,            qh + (size_t)row * HD + sg);
            cp16(d + 9216 * 2, ql + (size_t)row * HD + sg);
        }
    }
    auto issueKV = [&](int kb) {
        const uint32_t st = sb + (18432 + (kb & 1) * 9216) * 2;
        const int s0 = kb * 64;
        const __half* kh = g_Kh + ((size_t)bh * TT + s0) * HD;
        const __half* vh = g_Vh + (size_t)bh * HD * TT + s0;
        #pragma unroll
        for (int it = 0; it < 2; ++it) {
            const int f = tid + it * 256;
            const int row = f >> 3, sg = (f & 7) << 3;   // row 0..63
            cp16(st + (row * AP + sg) * 2,          kh + (size_t)row * HD + sg);
            cp16(st + ((4608 + row * AP + sg)) * 2, vh + (size_t)row * TT + sg);
        }
    };

    issueKV(0); CP_COMMIT();

    // ldmatrix per-lane offsets
    const int qRow = wid * 16 + (lane & 15);
    const int qK   = (lane >> 4) << 3;
    const int nRow = (lane & 7) + ((lane >> 4) << 3);
    const int nK   = ((lane >> 3) & 1) << 3;

    float m_i0 = -1e30f, m_i1 = -1e30f, l_i0 = 0.f, l_i1 = 0.f;
    float oacc[8][4];
    #pragma unroll
    for (int nc = 0; nc < 8; ++nc)
        #pragma unroll
        for (int r = 0; r < 4; ++r) oacc[nc][r] = 0.f;

    for (int kb = 0; kb < 16; ++kb) {
        if (kb < 15) { issueKV(kb + 1); CP_COMMIT(); CP_WAIT(1); }
        else         { CP_WAIT(0); }
        __syncthreads();
        const uint32_t st = sb + (18432 + (kb & 1) * 9216) * 2;

        // ---- S = Q K^T : (Qh + Ql) x Kh
        float sacc[8][4];
        #pragma unroll
        for (int ni = 0; ni < 8; ++ni)
            #pragma unroll
            for (int r = 0; r < 4; ++r) sacc[ni][r] = 0.f;

        #pragma unroll
        for (int ks = 0; ks < 4; ++ks) {
            const uint32_t qo = sb + ((qRow * AP) + ks * 16 + qK) * 2;
            uint32_t ah[4], al[4];
            ldsm4(ah, qo);
            ldsm4(al, qo + 9216 * 2);
            #pragma unroll
            for (int nj = 0; nj < 4; ++nj) {
                uint32_t kb4[4];
                ldsm4(kb4, st + (((nj * 16 + nRow) * AP) + ks * 16 + nK) * 2);
                mma16816(sacc[nj * 2 + 0], ah, kb4[0], kb4[1]);
                mma16816(sacc[nj * 2 + 0], al, kb4[0], kb4[1]);
                mma16816(sacc[nj * 2 + 1], ah, kb4[2], kb4[3]);
                mma16816(sacc[nj * 2 + 1], al, kb4[2], kb4[3]);
            }
        }
        // fold the hd^-0.5 score scale here (fp32, exactly equivalent)
        #pragma unroll
        for (int ni = 0; ni < 8; ++ni)
            #pragma unroll
            for (int r = 0; r < 4; ++r) sacc[ni][r] *= 0.125f;

        // ---- online softmax (rows g and g+8)
        float mx0 = -1e30f, mx1 = -1e30f;
        #pragma unroll
        for (int ni = 0; ni < 8; ++ni) {
            mx0 = fmaxf(mx0, fmaxf(sacc[ni][0], sacc[ni][1]));
            mx1 = fmaxf(mx1, fmaxf(sacc[ni][2], sacc[ni][3]));
        }
        mx0 = fmaxf(mx0, __shfl_xor_sync(0xffffffffu, mx0, 1));
        mx0 = fmaxf(mx0, __shfl_xor_sync(0xffffffffu, mx0, 2));
        mx1 = fmaxf(mx1, __shfl_xor_sync(0xffffffffu, mx1, 1));
        mx1 = fmaxf(mx1, __shfl_xor_sync(0xffffffffu, mx1, 2));
        const float mn0 = fmaxf(m_i0, mx0), mn1 = fmaxf(m_i1, mx1);
        const float c0 = __expf(m_i0 - mn0), c1 = __expf(m_i1 - mn1);
        m_i0 = mn0; m_i1 = mn1;
        float rs0 = 0.f, rs1 = 0.f;
        uint32_t pfrag[8][2];
        #pragma unroll
        for (int ni = 0; ni < 8; ++ni) {
            const float p0 = __expf(sacc[ni][0] - mn0);
            const float p1 = __expf(sacc[ni][1] - mn0);
            const float p2 = __expf(sacc[ni][2] - mn1);
            const float p3 = __expf(sacc[ni][3] - mn1);
            rs0 += p0 + p1; rs1 += p2 + p3;
            __half2 h0 = __floats2half2_rn(p0, p1);
            __half2 h1 = __floats2half2_rn(p2, p3);
            pfrag[ni][0] = *reinterpret_cast<uint32_t*>(&h0);
            pfrag[ni][1] = *reinterpret_cast<uint32_t*>(&h1);
        }
        rs0 += __shfl_xor_sync(0xffffffffu, rs0, 1);
        rs0 += __shfl_xor_sync(0xffffffffu, rs0, 2);
        rs1 += __shfl_xor_sync(0xffffffffu, rs1, 1);
        rs1 += __shfl_xor_sync(0xffffffffu, rs1, 2);
        l_i0 = l_i0 * c0 + rs0;
        l_i1 = l_i1 * c1 + rs1;
        #pragma unroll
        for (int nc = 0; nc < 8; ++nc) {
            oacc[nc][0] *= c0; oacc[nc][1] *= c0;
            oacc[nc][2] *= c1; oacc[nc][3] *= c1;
        }

        // ---- O += P Vh^T (1-term)
        #pragma unroll
        for (int ks = 0; ks < 4; ++ks) {
            const uint32_t pa[4] = { pfrag[2 * ks][0], pfrag[2 * ks][1],
                                     pfrag[2 * ks + 1][0], pfrag[2 * ks + 1][1] };
            #pragma unroll
            for (int nj = 0; nj < 4; ++nj) {
                uint32_t vb4[4];
                ldsm4(vb4, st + (((4608) + (nj * 16 + nRow) * AP) + ks * 16 + nK) * 2);
                mma16816(oacc[nj * 2 + 0], pa, vb4[0], vb4[1]);
                mma16816(oacc[nj * 2 + 1], pa, vb4[2], vb4[3]);
            }
        }
        __syncthreads();
    }

    // ---- epilogue: O/l split to fp16, store [b][t][c]
    const float inv0 = 1.f / l_i0, inv1 = 1.f / l_i1;
    #pragma unroll
    for (int nc = 0; nc < 8; ++nc) {
        uint32_t h, l;
        const size_t off0 = ((size_t)b * TT + t0 + wid * 16 + g) * CH
                          + head * 64 + nc * 8 + tig * 2;
        split2(oacc[nc][0] * inv0, oacc[nc][1] * inv0, h, l);
        *(uint32_t*)(g_hh + off0) = h;
        *(uint32_t*)(g_hl + off0) = l;
        const size_t off1 = off0 + (size_t)8 * CH;
        split2(oacc[nc][2] * inv1, oacc[nc][3] * inv1, h, l);
        *(uint32_t*)(g_hh + off1) = h;
        *(uint32_t*)(g_hl + off1) = l;
    }
}

// ---------------- launch ----------------------------------------------------------
extern "C" void kernel_launch(void* const* d_in, const int* in_sizes, int n_in,
                              void* d_out, int out_size) {
    const float* x    = (const float*)d_in[0];
    const float* nw   = (const float*)d_in[1];
    const float* nb   = (const float*)d_in[2];
    const float* qkvw = (const float*)d_in[3];
    const float* qkvb = (const float*)d_in[4];
    const float* pw   = (const float*)d_in[5];
    const float* pb   = (const float*)d_in[6];
    float* out = (float*)d_out;

    cudaFuncSetAttribute(hgemm_kernel<false>,
                         cudaFuncAttributeMaxDynamicSharedMemorySize, GEMM_SMEM);
    cudaFuncSetAttribute(hgemm_kernel<true>,
                         cudaFuncAttributeMaxDynamicSharedMemorySize, GEMM_SMEM);
    cudaFuncSetAttribute(attn_kernel,
                         cudaFuncAttributeMaxDynamicSharedMemorySize, ATTN_SMEM);

    gn_stats_kernel<<<BATCH * 32, 256>>>(x);
    w_pack_kernel<<<(3 * CH * CH + CH * CH) / 2 / 256, 256>>>(qkvw, pw);
    x_pack_kernel<<<dim3(16, 8, 16), 256>>>(x, nw, nb);
    hgemm_kernel<false><<<dim3(8, 12, BATCH), 256, GEMM_SMEM>>>(qkvb, nullptr, nullptr);
    attn_kernel<<<dim3(8, NHEAD, BATCH), 256, ATTN_SMEM>>>();
    hgemm_kernel<true><<<dim3(8, 4, BATCH), 256, GEMM_SMEM>>>(pb, x, out);
}

// round 9
// speedup vs baseline: 4.0618x; 1.1968x over previous
#include <cuda_runtime.h>
#include <cuda_fp16.h>
#include <stdint.h>
#include <math.h>

#define BATCH 16
#define CH    512
#define TT    1024
#define NHEAD 8
#define BHD   (BATCH * NHEAD)
#define HD    64

// ---------------- scratch ----------------------------------------------------
__device__ float g_mean[BATCH * 32];
__device__ float g_rstd[BATCH * 32];
__device__ __half g_Xh[(size_t)BATCH * TT * CH], g_Xl[(size_t)BATCH * TT * CH];
__device__ __half g_Whq[3 * CH * CH];
__device__ __half g_Whp[CH * CH], g_Wlp[CH * CH];
__device__ __half g_Qh[(size_t)BHD * TT * HD], g_Ql[(size_t)BHD * TT * HD];
__device__ __half g_Kh[(size_t)BHD * TT * HD];
__device__ __half g_Vh[(size_t)BHD * HD * TT];
__device__ __half g_hh[(size_t)BATCH * TT * CH];

// ---------------- helpers ------------------------------------------------------
__device__ __forceinline__ void split2(float a, float b, uint32_t& hi, uint32_t& lo) {
    __half2 h = __floats2half2_rn(a, b);
    float2 hf = __half22float2(h);
    __half2 l = __floats2half2_rn(a - hf.x, b - hf.y);
    hi = *reinterpret_cast<uint32_t*>(&h);
    lo = *reinterpret_cast<uint32_t*>(&l);
}
__device__ __forceinline__ void mma16816(float c[4], const uint32_t a[4],
                                         uint32_t b0, uint32_t b1) {
    asm volatile(
        "mma.sync.aligned.m16n8k16.row.col.f32.f16.f16.f32 "
        "{%0,%1,%2,%3}, {%4,%5,%6,%7}, {%8,%9}, {%0,%1,%2,%3};"
        : "+f"(c[0]), "+f"(c[1]), "+f"(c[2]), "+f"(c[3])
        : "r"(a[0]), "r"(a[1]), "r"(a[2]), "r"(a[3]), "r"(b0), "r"(b1));
}
__device__ __forceinline__ void ldsm4(uint32_t r[4], uint32_t addr) {
    asm volatile("ldmatrix.sync.aligned.m8n8.x4.shared.b16 {%0,%1,%2,%3}, [%4];"
                 : "=r"(r[0]), "=r"(r[1]), "=r"(r[2]), "=r"(r[3]) : "r"(addr));
}
__device__ __forceinline__ uint32_t smem_u32(const void* p) {
    uint32_t a;
    asm("{ .reg .u64 t; cvta.to.shared.u64 t, %1; cvt.u32.u64 %0, t; }"
        : "=r"(a) : "l"(p));
    return a;
}
__device__ __forceinline__ void cp16(uint32_t d, const void* s) {
    asm volatile("cp.async.cg.shared.global [%0], [%1], 16;" :: "r"(d), "l"(s));
}
#define CP_COMMIT() asm volatile("cp.async.commit_group;" ::: "memory")
#define CP_WAIT(n)  asm volatile("cp.async.wait_group %0;" :: "n"(n) : "memory")

// ---------------- GroupNorm statistics -----------------------------------------
__global__ void gn_stats_kernel(const float* __restrict__ x) {
    const int bg = blockIdx.x;
    const float4* base = (const float4*)(x + (size_t)bg * 16 * TT);
    float s = 0.f, ss = 0.f;
    for (int i = threadIdx.x; i < 4096; i += 256) {
        float4 v = base[i];
        s  += v.x + v.y + v.z + v.w;
        ss += v.x*v.x + v.y*v.y + v.z*v.z + v.w*v.w;
    }
    #pragma unroll
    for (int o = 16; o; o >>= 1) {
        s  += __shfl_down_sync(0xffffffffu, s,  o);
        ss += __shfl_down_sync(0xffffffffu, ss, o);
    }
    __shared__ float sh[16];
    const int w = threadIdx.x >> 5, l = threadIdx.x & 31;
    if (l == 0) { sh[w] = s; sh[8 + w] = ss; }
    __syncthreads();
    if (threadIdx.x == 0) {
        float S = 0.f, SS = 0.f;
        #pragma unroll
        for (int i = 0; i < 8; i++) { S += sh[i]; SS += sh[8 + i]; }
        const float mean = S * (1.f / 16384.f);
        const float var  = SS * (1.f / 16384.f) - mean * mean;
        g_mean[bg] = mean;
        g_rstd[bg] = rsqrtf(var + 1e-5f);
    }
}

// ---------------- weight pack ----------------------------------------------------
__global__ void w_pack_kernel(const float* __restrict__ qw,
                              const float* __restrict__ pw) {
    const int i = blockIdx.x * 256 + threadIdx.x;
    const int NQ = 3 * CH * CH / 2;
    uint32_t h, l;
    if (i < NQ) {
        float2 v = ((const float2*)qw)[i];
        split2(v.x, v.y, h, l);
        ((uint32_t*)g_Whq)[i] = h;            // qkv is 2-term: W-lo dropped
    } else {
        const int j = i - NQ;
        float2 v = ((const float2*)pw)[j];
        split2(v.x, v.y, h, l);
        ((uint32_t*)g_Whp)[j] = h;
        ((uint32_t*)g_Wlp)[j] = l;
    }
}

// ---------------- x pack: GroupNorm + split + transpose -> [b][t][c] ------------
__global__ void x_pack_kernel(const float* __restrict__ x,
                              const float* __restrict__ nw,
                              const float* __restrict__ nb) {
    __shared__ float tile[64][68];
    const int t0 = blockIdx.x * 64, c0 = blockIdx.y * 64, b = blockIdx.z;
    const int tid = threadIdx.x;
    const float* xb = x + (size_t)b * CH * TT;
    #pragma unroll
    for (int it = 0; it < 4; ++it) {
        const int f = tid + it * 256;
        const int cl = f >> 4, t4 = (f & 15) << 2;
        const int c = c0 + cl;
        float4 v = *(const float4*)(xb + (size_t)c * TT + t0 + t4);
        const int bg = (b << 5) + (c >> 4);
        const float w  = nw[c] * g_rstd[bg];
        const float bb = fmaf(-g_mean[bg], w, nb[c]);
        tile[cl][t4 + 0] = fmaf(v.x, w, bb);
        tile[cl][t4 + 1] = fmaf(v.y, w, bb);
        tile[cl][t4 + 2] = fmaf(v.z, w, bb);
        tile[cl][t4 + 3] = fmaf(v.w, w, bb);
    }
    __syncthreads();
    #pragma unroll
    for (int it = 0; it < 4; ++it) {
        const int f = tid + it * 256;
        const int tl = f >> 4, c4 = (f & 15) << 2;
        uint32_t h0, l0, h1, l1;
        split2(tile[c4 + 0][tl], tile[c4 + 1][tl], h0, l0);
        split2(tile[c4 + 2][tl], tile[c4 + 3][tl], h1, l1);
        const size_t off = ((size_t)b * TT + t0 + tl) * CH + c0 + c4;
        *(uint2*)(g_Xh + off) = make_uint2(h0, h1);
        *(uint2*)(g_Xl + off) = make_uint2(l0, l1);
    }
}

// ---------------- HMMA GEMM (split-fp16 2-term), 3-stage cp.async ring ----------
// qkv (IS_PROJ=0): A = gn(x) rows t (hi+lo), B = Wq rows m (hi); frag = [t][m].
// proj (IS_PROJ=1): A = Wp rows m (hi+lo), B = h rows t (hi);  frag = [m][t].
#define GP 40
#define GSB (128 * GP)                 // 5120 halves per array
#define GSTG (3 * GSB * 2)             // 30720 B per stage (Ah, Al, Bh)
#define GEMM_SMEM (3 * GSTG)           // 92160 B

template<bool IS_PROJ>
__global__ __launch_bounds__(256, 2)
void hgemm_kernel(const float* __restrict__ bias,
                  const float* __restrict__ resid,
                  float* __restrict__ outp) {
    extern __shared__ __half smh[];
    const uint32_t sb = smem_u32(smh);
    const int tid = threadIdx.x, lane = tid & 31, wid = tid >> 5;
    const int g = lane >> 2, tig = lane & 3;
    const int b = blockIdx.z;
    const int r0 = (IS_PROJ ? blockIdx.y : blockIdx.x) * 128;
    const int c0 = (IS_PROJ ? blockIdx.x : blockIdx.y) * 128;
    const int warp_m = wid >> 2, warp_n = wid & 3;

    const __half *pAh, *pAl, *pBh;
    if (IS_PROJ) {
        pAh = g_Whp + (size_t)r0 * CH;            pAl = g_Wlp + (size_t)r0 * CH;
        pBh = g_hh + ((size_t)b * TT + c0) * CH;
    } else {
        pAh = g_Xh + ((size_t)b * TT + r0) * CH;  pAl = g_Xl + ((size_t)b * TT + r0) * CH;
        pBh = g_Whq + (size_t)c0 * CH;
    }

    float acc[4][4][4];
    #pragma unroll
    for (int mi = 0; mi < 4; ++mi)
        #pragma unroll
        for (int ni = 0; ni < 4; ++ni)
            #pragma unroll
            for (int r = 0; r < 4; ++r) acc[mi][ni][r] = 0.f;

    const int aRow = warp_m * 64 + (lane & 15);
    const int aK   = (lane >> 4) << 3;
    const int bRow = warp_n * 32 + (lane & 7) + ((lane >> 4) << 3);
    const int bK   = ((lane >> 3) & 1) << 3;

    auto issue = [&](int ck) {
        const uint32_t st = sb + (ck % 3) * GSTG;
        const int k0 = ck * 32;
        #pragma unroll
        for (int it = 0; it < 2; ++it) {
            const int f = tid + it * 256;
            const int row = f >> 2, sg = (f & 3) << 3;
            const uint32_t da = st + (row * GP + sg) * 2;
            cp16(da,               pAh + (size_t)row * CH + k0 + sg);
            cp16(da + GSB * 2,     pAl + (size_t)row * CH + k0 + sg);
            cp16(da + 2 * GSB * 2, pBh + (size_t)row * CH + k0 + sg);
        }
    };

    auto compute = [&](int ck) {
        const uint32_t st = sb + (ck % 3) * GSTG;
        const uint32_t aH = st, aL = st + GSB * 2, bH = st + 2 * GSB * 2;
        #pragma unroll
        for (int kk = 0; kk < 32; kk += 16) {
            uint32_t afh[4][4], afl[4][4];
            #pragma unroll
            for (int mi = 0; mi < 4; ++mi) {
                const uint32_t ao = ((aRow + mi * 16) * GP + kk + aK) * 2;
                ldsm4(afh[mi], aH + ao);
                ldsm4(afl[mi], aL + ao);
            }
            #pragma unroll
            for (int nj = 0; nj < 2; ++nj) {
                uint32_t bfh[4];
                ldsm4(bfh, bH + ((bRow + nj * 16) * GP + kk + bK) * 2);
                #pragma unroll
                for (int mi = 0; mi < 4; ++mi) {
                    mma16816(acc[mi][nj * 2 + 0], afh[mi], bfh[0], bfh[1]);
                    mma16816(acc[mi][nj * 2 + 0], afl[mi], bfh[0], bfh[1]);
                    mma16816(acc[mi][nj * 2 + 1], afh[mi], bfh[2], bfh[3]);
                    mma16816(acc[mi][nj * 2 + 1], afl[mi], bfh[2], bfh[3]);
                }
            }
        }
    };

    issue(0); CP_COMMIT();
    issue(1); CP_COMMIT();
    for (int ck = 0; ck < 16; ++ck) {
        if (ck < 15) CP_WAIT(1); else CP_WAIT(0);
        __syncthreads();
        if (ck < 14) { issue(ck + 2); CP_COMMIT(); }
        compute(ck);
    }

    if (IS_PROJ) {
        const int mbase = r0 + warp_m * 64;
        const int nbase = c0 + warp_n * 32;
        const float* xres = resid + (size_t)b * CH * TT;
        float* ob = outp + (size_t)b * CH * TT;
        #pragma unroll
        for (int mi = 0; mi < 4; ++mi) {
            const int mA = mbase + mi * 16 + g;
            const int mB = mA + 8;
            const float biA = bias[mA], biB = bias[mB];
            #pragma unroll
            for (int ni = 0; ni < 4; ++ni) {
                const int t = nbase + ni * 8 + tig * 2;
                float2 v0, v1;
                v0.x = acc[mi][ni][0] + biA; v0.y = acc[mi][ni][1] + biA;
                v1.x = acc[mi][ni][2] + biB; v1.y = acc[mi][ni][3] + biB;
                float2 r0v = *(const float2*)(xres + (size_t)mA * TT + t);
                float2 r1v = *(const float2*)(xres + (size_t)mB * TT + t);
                v0.x += r0v.x; v0.y += r0v.y;
                v1.x += r1v.x; v1.y += r1v.y;
                *(float2*)(ob + (size_t)mA * TT + t) = v0;
                *(float2*)(ob + (size_t)mB * TT + t) = v1;
            }
        }
    } else {
        #pragma unroll
        for (int ni = 0; ni < 4; ++ni) {
            const int m = c0 + warp_n * 32 + ni * 8 + tig * 2;
            const int head = m / 192;
            const int rmod = m - head * 192;
            const int kind = rmod >> 6, c = rmod & 63;
            const int bh = b * NHEAD + head;
            const float b0v = bias[m], b1v = bias[m + 1];
            #pragma unroll
            for (int mi = 0; mi < 4; ++mi) {
                #pragma unroll
                for (int rr = 0; rr < 2; ++rr) {
                    const int t = r0 + warp_m * 64 + mi * 16 + g + rr * 8;
                    const float v0 = acc[mi][ni][rr * 2 + 0] + b0v;
                    const float v1 = acc[mi][ni][rr * 2 + 1] + b1v;
                    if (kind == 0) {
                        uint32_t h, l; split2(v0, v1, h, l);
                        const size_t off = ((size_t)bh * TT + t) * HD + c;
                        *(uint32_t*)(g_Qh + off) = h;
                        *(uint32_t*)(g_Ql + off) = l;
                    } else if (kind == 1) {
                        __half2 h2 = __floats2half2_rn(v0, v1);
                        *(__half2*)(g_Kh + ((size_t)bh * TT + t) * HD + c) = h2;
                    } else {
                        g_Vh[((size_t)bh * HD + c) * TT + t]     = __float2half_rn(v0);
                        g_Vh[((size_t)bh * HD + c + 1) * TT + t] = __float2half_rn(v1);
                    }
                }
            }
        }
    }
}

// ---------------- HMMA flash attention (QK 2-term, PV 1-term), 3-stage ring -----
// smem halves: Qh @0 (128x72), Ql @9216; stage k @18432+(k%3)*9216: Kh +0, Vh +4608.
#define AP 72
#define ATTN_SMEM ((18432 + 3 * 9216) * 2)   // 92160 B

__global__ __launch_bounds__(256)
void attn_kernel() {
    extern __shared__ __half sa[];
    const uint32_t sb = smem_u32(sa);
    const int tid = threadIdx.x, lane = tid & 31, wid = tid >> 5;
    const int g = lane >> 2, tig = lane & 3;
    const int tblk = blockIdx.x, head = blockIdx.y, b = blockIdx.z;
    const int bh = b * NHEAD + head;
    const int t0 = tblk * 128;

    {   // Q hi+lo (part of cp.async group 0)
        const __half* qh = g_Qh + ((size_t)bh * TT + t0) * HD;
        const __half* ql = g_Ql + ((size_t)bh * TT + t0) * HD;
        #pragma unroll
        for (int it = 0; it < 4; ++it) {
            const int f = tid + it * 256;
            const int row = f >> 3, sg = (f & 7) << 3;
            const uint32_t d = sb + (row * AP + sg) * 2;
            cp16(d,            qh + (size_t)row * HD + sg);
            cp16(d + 9216 * 2, ql + (size_t)row * HD + sg);
        }
    }
    auto issueKV = [&](int kb) {
        const uint32_t st = sb + (18432 + (kb % 3) * 9216) * 2;
        const int s0 = kb * 64;
        const __half* kh = g_Kh + ((size_t)bh * TT + s0) * HD;
        const __half* vh = g_Vh + (size_t)bh * HD * TT + s0;
        #pragma unroll
        for (int it = 0; it < 2; ++it) {
            const int f = tid + it * 256;
            const int row = f >> 3, sg = (f & 7) << 3;
            cp16(st + (row * AP + sg) * 2,        kh + (size_t)row * HD + sg);
            cp16(st + (4608 + row * AP + sg) * 2, vh + (size_t)row * TT + sg);
        }
    };

    issueKV(0); CP_COMMIT();
    issueKV(1); CP_COMMIT();

    const int qRow = wid * 16 + (lane & 15);
    const int qK   = (lane >> 4) << 3;
    const int nRow = (lane & 7) + ((lane >> 4) << 3);
    const int nK   = ((lane >> 3) & 1) << 3;

    float m_i0 = -1e30f, m_i1 = -1e30f, l_i0 = 0.f, l_i1 = 0.f;
    float oacc[8][4];
    #pragma unroll
    for (int nc = 0; nc < 8; ++nc)
        #pragma unroll
        for (int r = 0; r < 4; ++r) oacc[nc][r] = 0.f;

    for (int kb = 0; kb < 16; ++kb) {
        if (kb < 15) CP_WAIT(1); else CP_WAIT(0);
        __syncthreads();
        if (kb < 14) { issueKV(kb + 2); CP_COMMIT(); }
        const uint32_t st = sb + (18432 + (kb % 3) * 9216) * 2;

        // ---- S = (Qh + Ql) Kh^T
        float sacc[8][4];
        #pragma unroll
        for (int ni = 0; ni < 8; ++ni)
            #pragma unroll
            for (int r = 0; r < 4; ++r) sacc[ni][r] = 0.f;

        #pragma unroll
        for (int ks = 0; ks < 4; ++ks) {
            const uint32_t qo = sb + ((qRow * AP) + ks * 16 + qK) * 2;
            uint32_t ah[4], al[4];
            ldsm4(ah, qo);
            ldsm4(al, qo + 9216 * 2);
            #pragma unroll
            for (int nj = 0; nj < 4; ++nj) {
                uint32_t kb4[4];
                ldsm4(kb4, st + (((nj * 16 + nRow) * AP) + ks * 16 + nK) * 2);
                mma16816(sacc[nj * 2 + 0], ah, kb4[0], kb4[1]);
                mma16816(sacc[nj * 2 + 0], al, kb4[0], kb4[1]);
                mma16816(sacc[nj * 2 + 1], ah, kb4[2], kb4[3]);
                mma16816(sacc[nj * 2 + 1], al, kb4[2], kb4[3]);
            }
        }
        #pragma unroll
        for (int ni = 0; ni < 8; ++ni)
            #pragma unroll
            for (int r = 0; r < 4; ++r) sacc[ni][r] *= 0.125f;

        // ---- online softmax
        float mx0 = -1e30f, mx1 = -1e30f;
        #pragma unroll
        for (int ni = 0; ni < 8; ++ni) {
            mx0 = fmaxf(mx0, fmaxf(sacc[ni][0], sacc[ni][1]));
            mx1 = fmaxf(mx1, fmaxf(sacc[ni][2], sacc[ni][3]));
        }
        mx0 = fmaxf(mx0, __shfl_xor_sync(0xffffffffu, mx0, 1));
        mx0 = fmaxf(mx0, __shfl_xor_sync(0xffffffffu, mx0, 2));
        mx1 = fmaxf(mx1, __shfl_xor_sync(0xffffffffu, mx1, 1));
        mx1 = fmaxf(mx1, __shfl_xor_sync(0xffffffffu, mx1, 2));
        const float mn0 = fmaxf(m_i0, mx0), mn1 = fmaxf(m_i1, mx1);
        const float c0 = __expf(m_i0 - mn0), c1 = __expf(m_i1 - mn1);
        m_i0 = mn0; m_i1 = mn1;
        float rs0 = 0.f, rs1 = 0.f;
        uint32_t pfrag[8][2];
        #pragma unroll
        for (int ni = 0; ni < 8; ++ni) {
            const float p0 = __expf(sacc[ni][0] - mn0);
            const float p1 = __expf(sacc[ni][1] - mn0);
            const float p2 = __expf(sacc[ni][2] - mn1);
            const float p3 = __expf(sacc[ni][3] - mn1);
            rs0 += p0 + p1; rs1 += p2 + p3;
            __half2 h0 = __floats2half2_rn(p0, p1);
            __half2 h1 = __floats2half2_rn(p2, p3);
            pfrag[ni][0] = *reinterpret_cast<uint32_t*>(&h0);
            pfrag[ni][1] = *reinterpret_cast<uint32_t*>(&h1);
        }
        rs0 += __shfl_xor_sync(0xffffffffu, rs0, 1);
        rs0 += __shfl_xor_sync(0xffffffffu, rs0, 2);
        rs1 += __shfl_xor_sync(0xffffffffu, rs1, 1);
        rs1 += __shfl_xor_sync(0xffffffffu, rs1, 2);
        l_i0 = l_i0 * c0 + rs0;
        l_i1 = l_i1 * c1 + rs1;
        #pragma unroll
        for (int nc = 0; nc < 8; ++nc) {
            oacc[nc][0] *= c0; oacc[nc][1] *= c0;
            oacc[nc][2] *= c1; oacc[nc][3] *= c1;
        }

        // ---- O += P Vh^T
        #pragma unroll
        for (int ks = 0; ks < 4; ++ks) {
            const uint32_t pa[4] = { pfrag[2 * ks][0], pfrag[2 * ks][1],
                                     pfrag[2 * ks + 1][0], pfrag[2 * ks + 1][1] };
            #pragma unroll
            for (int nj = 0; nj < 4; ++nj) {
                uint32_t vb4[4];
                ldsm4(vb4, st + ((4608 + (nj * 16 + nRow) * AP) + ks * 16 + nK) * 2);
                mma16816(oacc[nj * 2 + 0], pa, vb4[0], vb4[1]);
                mma16816(oacc[nj * 2 + 1], pa, vb4[2], vb4[3]);
            }
        }
    }

    // ---- epilogue: store fp16-hi h only, [b][t][c]
    const float inv0 = 1.f / l_i0, inv1 = 1.f / l_i1;
    #pragma unroll
    for (int nc = 0; nc < 8; ++nc) {
        const size_t off0 = ((size_t)b * TT + t0 + wid * 16 + g) * CH
                          + head * 64 + nc * 8 + tig * 2;
        __half2 h0 = __floats2half2_rn(oacc[nc][0] * inv0, oacc[nc][1] * inv0);
        *(__half2*)(g_hh + off0) = h0;
        const size_t off1 = off0 + (size_t)8 * CH;
        __half2 h1 = __floats2half2_rn(oacc[nc][2] * inv1, oacc[nc][3] * inv1);
        *(__half2*)(g_hh + off1) = h1;
    }
}

// ---------------- launch ----------------------------------------------------------
extern "C" void kernel_launch(void* const* d_in, const int* in_sizes, int n_in,
                              void* d_out, int out_size) {
    const float* x    = (const float*)d_in[0];
    const float* nw   = (const float*)d_in[1];
    const float* nb   = (const float*)d_in[2];
    const float* qkvw = (const float*)d_in[3];
    const float* qkvb = (const float*)d_in[4];
    const float* pw   = (const float*)d_in[5];
    const float* pb   = (const float*)d_in[6];
    float* out = (float*)d_out;

    cudaFuncSetAttribute(hgemm_kernel<false>,
                         cudaFuncAttributeMaxDynamicSharedMemorySize, GEMM_SMEM);
    cudaFuncSetAttribute(hgemm_kernel<true>,
                         cudaFuncAttributeMaxDynamicSharedMemorySize, GEMM_SMEM);
    cudaFuncSetAttribute(attn_kernel,
                         cudaFuncAttributeMaxDynamicSharedMemorySize, ATTN_SMEM);

    gn_stats_kernel<<<BATCH * 32, 256>>>(x);
    w_pack_kernel<<<(3 * CH * CH + CH * CH) / 2 / 256, 256>>>(qkvw, pw);
    x_pack_kernel<<<dim3(16, 8, 16), 256>>>(x, nw, nb);
    hgemm_kernel<false><<<dim3(8, 12, BATCH), 256, GEMM_SMEM>>>(qkvb, nullptr, nullptr);
    attn_kernel<<<dim3(8, NHEAD, BATCH), 256, ATTN_SMEM>>>();
    hgemm_kernel<true><<<dim3(8, 4, BATCH), 256, GEMM_SMEM>>>(pb, x, out);
}

// round 10
// speedup vs baseline: 5.5372x; 1.3632x over previous
#include <cuda_runtime.h>
#include <cuda_fp16.h>
#include <stdint.h>
#include <math.h>

#define BATCH 16
#define CH    512
#define TT    1024
#define NHEAD 8
#define BHD   (BATCH * NHEAD)
#define HD    64

// ---------------- scratch ----------------------------------------------------
__device__ float g_mean[BATCH * 32];
__device__ float g_rstd[BATCH * 32];
__device__ __half g_Xh[(size_t)BATCH * TT * CH];
__device__ __half g_Whq[3 * CH * CH];
__device__ __half g_Whp[CH * CH], g_Wlp[CH * CH];
__device__ __half g_Qh[(size_t)BHD * TT * HD];
__device__ __half g_Kh[(size_t)BHD * TT * HD];
__device__ __half g_Vh[(size_t)BHD * HD * TT];
__device__ __half g_hh[(size_t)BATCH * TT * CH];

// ---------------- helpers ------------------------------------------------------
__device__ __forceinline__ void split2(float a, float b, uint32_t& hi, uint32_t& lo) {
    __half2 h = __floats2half2_rn(a, b);
    float2 hf = __half22float2(h);
    __half2 l = __floats2half2_rn(a - hf.x, b - hf.y);
    hi = *reinterpret_cast<uint32_t*>(&h);
    lo = *reinterpret_cast<uint32_t*>(&l);
}
__device__ __forceinline__ void mma16816(float c[4], const uint32_t a[4],
                                         uint32_t b0, uint32_t b1) {
    asm volatile(
        "mma.sync.aligned.m16n8k16.row.col.f32.f16.f16.f32 "
        "{%0,%1,%2,%3}, {%4,%5,%6,%7}, {%8,%9}, {%0,%1,%2,%3};"
        : "+f"(c[0]), "+f"(c[1]), "+f"(c[2]), "+f"(c[3])
        : "r"(a[0]), "r"(a[1]), "r"(a[2]), "r"(a[3]), "r"(b0), "r"(b1));
}
__device__ __forceinline__ void ldsm4(uint32_t r[4], uint32_t addr) {
    asm volatile("ldmatrix.sync.aligned.m8n8.x4.shared.b16 {%0,%1,%2,%3}, [%4];"
                 : "=r"(r[0]), "=r"(r[1]), "=r"(r[2]), "=r"(r[3]) : "r"(addr));
}
__device__ __forceinline__ uint32_t smem_u32(const void* p) {
    uint32_t a;
    asm("{ .reg .u64 t; cvta.to.shared.u64 t, %1; cvt.u32.u64 %0, t; }"
        : "=r"(a) : "l"(p));
    return a;
}
__device__ __forceinline__ void cp16(uint32_t d, const void* s) {
    asm volatile("cp.async.cg.shared.global [%0], [%1], 16;" :: "r"(d), "l"(s));
}
#define CP_COMMIT() asm volatile("cp.async.commit_group;" ::: "memory")
#define CP_WAIT(n)  asm volatile("cp.async.wait_group %0;" :: "n"(n) : "memory")

// ---------------- GroupNorm statistics -----------------------------------------
__global__ void gn_stats_kernel(const float* __restrict__ x) {
    const int bg = blockIdx.x;
    const float4* base = (const float4*)(x + (size_t)bg * 16 * TT);
    float s = 0.f, ss = 0.f;
    for (int i = threadIdx.x; i < 4096; i += 256) {
        float4 v = base[i];
        s  += v.x + v.y + v.z + v.w;
        ss += v.x*v.x + v.y*v.y + v.z*v.z + v.w*v.w;
    }
    #pragma unroll
    for (int o = 16; o; o >>= 1) {
        s  += __shfl_down_sync(0xffffffffu, s,  o);
        ss += __shfl_down_sync(0xffffffffu, ss, o);
    }
    __shared__ float sh[16];
    const int w = threadIdx.x >> 5, l = threadIdx.x & 31;
    if (l == 0) { sh[w] = s; sh[8 + w] = ss; }
    __syncthreads();
    if (threadIdx.x == 0) {
        float S = 0.f, SS = 0.f;
        #pragma unroll
        for (int i = 0; i < 8; i++) { S += sh[i]; SS += sh[8 + i]; }
        const float mean = S * (1.f / 16384.f);
        const float var  = SS * (1.f / 16384.f) - mean * mean;
        g_mean[bg] = mean;
        g_rstd[bg] = rsqrtf(var + 1e-5f);
    }
}

// ---------------- weight pack ----------------------------------------------------
__global__ void w_pack_kernel(const float* __restrict__ qw,
                              const float* __restrict__ pw) {
    const int i = blockIdx.x * 256 + threadIdx.x;
    const int NQ = 3 * CH * CH / 2;
    uint32_t h, l;
    if (i < NQ) {
        float2 v = ((const float2*)qw)[i];
        split2(v.x, v.y, h, l);
        ((uint32_t*)g_Whq)[i] = h;             // qkv GEMM is 1-term
    } else {
        const int j = i - NQ;
        float2 v = ((const float2*)pw)[j];
        split2(v.x, v.y, h, l);
        ((uint32_t*)g_Whp)[j] = h;             // proj GEMM stays 2-term
        ((uint32_t*)g_Wlp)[j] = l;
    }
}

// ---------------- x pack: GroupNorm + fp16 + transpose -> [b][t][c] -------------
__global__ void x_pack_kernel(const float* __restrict__ x,
                              const float* __restrict__ nw,
                              const float* __restrict__ nb) {
    __shared__ float tile[64][68];
    const int t0 = blockIdx.x * 64, c0 = blockIdx.y * 64, b = blockIdx.z;
    const int tid = threadIdx.x;
    const float* xb = x + (size_t)b * CH * TT;
    #pragma unroll
    for (int it = 0; it < 4; ++it) {
        const int f = tid + it * 256;
        const int cl = f >> 4, t4 = (f & 15) << 2;
        const int c = c0 + cl;
        float4 v = *(const float4*)(xb + (size_t)c * TT + t0 + t4);
        const int bg = (b << 5) + (c >> 4);
        const float w  = nw[c] * g_rstd[bg];
        const float bb = fmaf(-g_mean[bg], w, nb[c]);
        tile[cl][t4 + 0] = fmaf(v.x, w, bb);
        tile[cl][t4 + 1] = fmaf(v.y, w, bb);
        tile[cl][t4 + 2] = fmaf(v.z, w, bb);
        tile[cl][t4 + 3] = fmaf(v.w, w, bb);
    }
    __syncthreads();
    #pragma unroll
    for (int it = 0; it < 4; ++it) {
        const int f = tid + it * 256;
        const int tl = f >> 4, c4 = (f & 15) << 2;
        __half2 h0 = __floats2half2_rn(tile[c4 + 0][tl], tile[c4 + 1][tl]);
        __half2 h1 = __floats2half2_rn(tile[c4 + 2][tl], tile[c4 + 3][tl]);
        const size_t off = ((size_t)b * TT + t0 + tl) * CH + c0 + c4;
        *(uint2*)(g_Xh + off) = make_uint2(*(uint32_t*)&h0, *(uint32_t*)&h1);
    }
}

// ---------------- HMMA GEMM, 3-stage cp.async ring -------------------------------
// qkv (IS_PROJ=0): 1-term, A = Xh rows t, B = Whq rows m; frag = [t][m];
//                  epilogue packs Q/K/V fp16 directly.
// proj (IS_PROJ=1): 2-term, A = Wp rows m (hi+lo), B = hh rows t; fp32 out + resid.
#define GP 40
#define GSB (128 * GP)                 // 5120 halves per array

template<bool IS_PROJ>
__global__ __launch_bounds__(256, 2)
void hgemm_kernel(const float* __restrict__ bias,
                  const float* __restrict__ resid,
                  float* __restrict__ outp) {
    constexpr int NARR = IS_PROJ ? 3 : 2;
    constexpr uint32_t GSTG = NARR * GSB * 2;   // bytes per stage
    extern __shared__ __half smh[];
    const uint32_t sb = smem_u32(smh);
    const int tid = threadIdx.x, lane = tid & 31, wid = tid >> 5;
    const int g = lane >> 2, tig = lane & 3;
    const int b = blockIdx.z;
    const int r0 = (IS_PROJ ? blockIdx.y : blockIdx.x) * 128;
    const int c0 = (IS_PROJ ? blockIdx.x : blockIdx.y) * 128;
    const int warp_m = wid >> 2, warp_n = wid & 3;

    const __half *pAh, *pAl, *pBh;
    if (IS_PROJ) {
        pAh = g_Whp + (size_t)r0 * CH;  pAl = g_Wlp + (size_t)r0 * CH;
        pBh = g_hh + ((size_t)b * TT + c0) * CH;
    } else {
        pAh = g_Xh + ((size_t)b * TT + r0) * CH;  pAl = nullptr;
        pBh = g_Whq + (size_t)c0 * CH;
    }

    float acc[4][4][4];
    #pragma unroll
    for (int mi = 0; mi < 4; ++mi)
        #pragma unroll
        for (int ni = 0; ni < 4; ++ni)
            #pragma unroll
            for (int r = 0; r < 4; ++r) acc[mi][ni][r] = 0.f;

    const int aRow = warp_m * 64 + (lane & 15);
    const int aK   = (lane >> 4) << 3;
    const int bRow = warp_n * 32 + (lane & 7) + ((lane >> 4) << 3);
    const int bK   = ((lane >> 3) & 1) << 3;

    auto issue = [&](int ck) {
        const uint32_t st = sb + (ck % 3) * GSTG;
        const int k0 = ck * 32;
        #pragma unroll
        for (int it = 0; it < 2; ++it) {
            const int f = tid + it * 256;
            const int row = f >> 2, sg = (f & 3) << 3;
            const uint32_t da = st + (row * GP + sg) * 2;
            cp16(da, pAh + (size_t)row * CH + k0 + sg);
            if (IS_PROJ) {
                cp16(da + GSB * 2,     pAl + (size_t)row * CH + k0 + sg);
                cp16(da + 2 * GSB * 2, pBh + (size_t)row * CH + k0 + sg);
            } else {
                cp16(da + GSB * 2,     pBh + (size_t)row * CH + k0 + sg);
            }
        }
    };

    auto compute = [&](int ck) {
        const uint32_t st = sb + (ck % 3) * GSTG;
        const uint32_t aH = st;
        const uint32_t aL = st + GSB * 2;                      // proj only
        const uint32_t bH = st + (NARR - 1) * GSB * 2;
        #pragma unroll
        for (int kk = 0; kk < 32; kk += 16) {
            uint32_t afh[4][4], afl[4][4];
            #pragma unroll
            for (int mi = 0; mi < 4; ++mi) {
                const uint32_t ao = ((aRow + mi * 16) * GP + kk + aK) * 2;
                ldsm4(afh[mi], aH + ao);
                if (IS_PROJ) ldsm4(afl[mi], aL + ao);
            }
            #pragma unroll
            for (int nj = 0; nj < 2; ++nj) {
                uint32_t bfh[4];
                ldsm4(bfh, bH + ((bRow + nj * 16) * GP + kk + bK) * 2);
                #pragma unroll
                for (int mi = 0; mi < 4; ++mi) {
                    mma16816(acc[mi][nj * 2 + 0], afh[mi], bfh[0], bfh[1]);
                    mma16816(acc[mi][nj * 2 + 1], afh[mi], bfh[2], bfh[3]);
                    if (IS_PROJ) {
                        mma16816(acc[mi][nj * 2 + 0], afl[mi], bfh[0], bfh[1]);
                        mma16816(acc[mi][nj * 2 + 1], afl[mi], bfh[2], bfh[3]);
                    }
                }
            }
        }
    };

    issue(0); CP_COMMIT();
    issue(1); CP_COMMIT();
    for (int ck = 0; ck < 16; ++ck) {
        if (ck < 15) CP_WAIT(1); else CP_WAIT(0);
        __syncthreads();
        if (ck < 14) { issue(ck + 2); CP_COMMIT(); }
        compute(ck);
    }

    if (IS_PROJ) {
        const int mbase = r0 + warp_m * 64;
        const int nbase = c0 + warp_n * 32;
        const float* xres = resid + (size_t)b * CH * TT;
        float* ob = outp + (size_t)b * CH * TT;
        #pragma unroll
        for (int mi = 0; mi < 4; ++mi) {
            const int mA = mbase + mi * 16 + g;
            const int mB = mA + 8;
            const float biA = bias[mA], biB = bias[mB];
            #pragma unroll
            for (int ni = 0; ni < 4; ++ni) {
                const int t = nbase + ni * 8 + tig * 2;
                float2 v0, v1;
                v0.x = acc[mi][ni][0] + biA; v0.y = acc[mi][ni][1] + biA;
                v1.x = acc[mi][ni][2] + biB; v1.y = acc[mi][ni][3] + biB;
                float2 r0v = *(const float2*)(xres + (size_t)mA * TT + t);
                float2 r1v = *(const float2*)(xres + (size_t)mB * TT + t);
                v0.x += r0v.x; v0.y += r0v.y;
                v1.x += r1v.x; v1.y += r1v.y;
                *(float2*)(ob + (size_t)mA * TT + t) = v0;
                *(float2*)(ob + (size_t)mB * TT + t) = v1;
            }
        }
    } else {
        #pragma unroll
        for (int ni = 0; ni < 4; ++ni) {
            const int m = c0 + warp_n * 32 + ni * 8 + tig * 2;
            const int head = m / 192;
            const int rmod = m - head * 192;
            const int kind = rmod >> 6, c = rmod & 63;
            const int bh = b * NHEAD + head;
            const float b0v = bias[m], b1v = bias[m + 1];
            #pragma unroll
            for (int mi = 0; mi < 4; ++mi) {
                #pragma unroll
                for (int rr = 0; rr < 2; ++rr) {
                    const int t = r0 + warp_m * 64 + mi * 16 + g + rr * 8;
                    const float v0 = acc[mi][ni][rr * 2 + 0] + b0v;
                    const float v1 = acc[mi][ni][rr * 2 + 1] + b1v;
                    if (kind == 0) {
                        __half2 h2 = __floats2half2_rn(v0, v1);
                        *(__half2*)(g_Qh + ((size_t)bh * TT + t) * HD + c) = h2;
                    } else if (kind == 1) {
                        __half2 h2 = __floats2half2_rn(v0, v1);
                        *(__half2*)(g_Kh + ((size_t)bh * TT + t) * HD + c) = h2;
                    } else {
                        g_Vh[((size_t)bh * HD + c) * TT + t]     = __float2half_rn(v0);
                        g_Vh[((size_t)bh * HD + c + 1) * TT + t] = __float2half_rn(v1);
                    }
                }
            }
        }
    }
}

// ---------------- HMMA flash attention (QK 1-term, PV 1-term), 3-stage ring -----
// smem halves: Qh @0 (128x72); stage k @9216+(k%3)*9216: Kh +0, Vh +4608.
#define AP 72
#define ATTN_SMEM ((9216 + 3 * 9216) * 2)   // 73728 B

__global__ __launch_bounds__(256)
void attn_kernel() {
    extern __shared__ __half sa[];
    const uint32_t sb = smem_u32(sa);
    const int tid = threadIdx.x, lane = tid & 31, wid = tid >> 5;
    const int g = lane >> 2, tig = lane & 3;
    const int tblk = blockIdx.x, head = blockIdx.y, b = blockIdx.z;
    const int bh = b * NHEAD + head;
    const int t0 = tblk * 128;

    {   // Q hi: 128 rows x 64 halves
        const __half* qh = g_Qh + ((size_t)bh * TT + t0) * HD;
        #pragma unroll
        for (int it = 0; it < 4; ++it) {
            const int f = tid + it * 256;
            const int row = f >> 3, sg = (f & 7) << 3;
            cp16(sb + (row * AP + sg) * 2, qh + (size_t)row * HD + sg);
        }
    }
    auto issueKV = [&](int kb) {
        const uint32_t st = sb + (9216 + (kb % 3) * 9216) * 2;
        const int s0 = kb * 64;
        const __half* kh = g_Kh + ((size_t)bh * TT + s0) * HD;
        const __half* vh = g_Vh + (size_t)bh * HD * TT + s0;
        #pragma unroll
        for (int it = 0; it < 2; ++it) {
            const int f = tid + it * 256;
            const int row = f >> 3, sg = (f & 7) << 3;
            cp16(st + (row * AP + sg) * 2,        kh + (size_t)row * HD + sg);
            cp16(st + (4608 + row * AP + sg) * 2, vh + (size_t)row * TT + sg);
        }
    };

    issueKV(0); CP_COMMIT();
    issueKV(1); CP_COMMIT();

    const int qRow = wid * 16 + (lane & 15);
    const int qK   = (lane >> 4) << 3;
    const int nRow = (lane & 7) + ((lane >> 4) << 3);
    const int nK   = ((lane >> 3) & 1) << 3;

    float m_i0 = -1e30f, m_i1 = -1e30f, l_i0 = 0.f, l_i1 = 0.f;
    float oacc[8][4];
    #pragma unroll
    for (int nc = 0; nc < 8; ++nc)
        #pragma unroll
        for (int r = 0; r < 4; ++r) oacc[nc][r] = 0.f;

    for (int kb = 0; kb < 16; ++kb) {
        if (kb < 15) CP_WAIT(1); else CP_WAIT(0);
        __syncthreads();
        if (kb < 14) { issueKV(kb + 2); CP_COMMIT(); }
        const uint32_t st = sb + (9216 + (kb % 3) * 9216) * 2;

        // ---- S = Qh Kh^T (1-term)
        float sacc[8][4];
        #pragma unroll
        for (int ni = 0; ni < 8; ++ni)
            #pragma unroll
            for (int r = 0; r < 4; ++r) sacc[ni][r] = 0.f;

        #pragma unroll
        for (int ks = 0; ks < 4; ++ks) {
            uint32_t ah[4];
            ldsm4(ah, sb + ((qRow * AP) + ks * 16 + qK) * 2);
            #pragma unroll
            for (int nj = 0; nj < 4; ++nj) {
                uint32_t kb4[4];
                ldsm4(kb4, st + (((nj * 16 + nRow) * AP) + ks * 16 + nK) * 2);
                mma16816(sacc[nj * 2 + 0], ah, kb4[0], kb4[1]);
                mma16816(sacc[nj * 2 + 1], ah, kb4[2], kb4[3]);
            }
        }
        #pragma unroll
        for (int ni = 0; ni < 8; ++ni)
            #pragma unroll
            for (int r = 0; r < 4; ++r) sacc[ni][r] *= 0.125f;

        // ---- online softmax (rows g and g+8)
        float mx0 = -1e30f, mx1 = -1e30f;
        #pragma unroll
        for (int ni = 0; ni < 8; ++ni) {
            mx0 = fmaxf(mx0, fmaxf(sacc[ni][0], sacc[ni][1]));
            mx1 = fmaxf(mx1, fmaxf(sacc[ni][2], sacc[ni][3]));
        }
        mx0 = fmaxf(mx0, __shfl_xor_sync(0xffffffffu, mx0, 1));
        mx0 = fmaxf(mx0, __shfl_xor_sync(0xffffffffu, mx0, 2));
        mx1 = fmaxf(mx1, __shfl_xor_sync(0xffffffffu, mx1, 1));
        mx1 = fmaxf(mx1, __shfl_xor_sync(0xffffffffu, mx1, 2));
        const float mn0 = fmaxf(m_i0, mx0), mn1 = fmaxf(m_i1, mx1);
        const float c0 = __expf(m_i0 - mn0), c1 = __expf(m_i1 - mn1);
        m_i0 = mn0; m_i1 = mn1;
        float rs0 = 0.f, rs1 = 0.f;
        uint32_t pfrag[8][2];
        #pragma unroll
        for (int ni = 0; ni < 8; ++ni) {
            const float p0 = __expf(sacc[ni][0] - mn0);
            const float p1 = __expf(sacc[ni][1] - mn0);
            const float p2 = __expf(sacc[ni][2] - mn1);
            const float p3 = __expf(sacc[ni][3] - mn1);
            rs0 += p0 + p1; rs1 += p2 + p3;
            __half2 h0 = __floats2half2_rn(p0, p1);
            __half2 h1 = __floats2half2_rn(p2, p3);
            pfrag[ni][0] = *reinterpret_cast<uint32_t*>(&h0);
            pfrag[ni][1] = *reinterpret_cast<uint32_t*>(&h1);
        }
        rs0 += __shfl_xor_sync(0xffffffffu, rs0, 1);
        rs0 += __shfl_xor_sync(0xffffffffu, rs0, 2);
        rs1 += __shfl_xor_sync(0xffffffffu, rs1, 1);
        rs1 += __shfl_xor_sync(0xffffffffu, rs1, 2);
        l_i0 = l_i0 * c0 + rs0;
        l_i1 = l_i1 * c1 + rs1;
        #pragma unroll
        for (int nc = 0; nc < 8; ++nc) {
            oacc[nc][0] *= c0; oacc[nc][1] *= c0;
            oacc[nc][2] *= c1; oacc[nc][3] *= c1;
        }

        // ---- O += P Vh^T
        #pragma unroll
        for (int ks = 0; ks < 4; ++ks) {
            const uint32_t pa[4] = { pfrag[2 * ks][0], pfrag[2 * ks][1],
                                     pfrag[2 * ks + 1][0], pfrag[2 * ks + 1][1] };
            #pragma unroll
            for (int nj = 0; nj < 4; ++nj) {
                uint32_t vb4[4];
                ldsm4(vb4, st + ((4608 + (nj * 16 + nRow) * AP) + ks * 16 + nK) * 2);
                mma16816(oacc[nj * 2 + 0], pa, vb4[0], vb4[1]);
                mma16816(oacc[nj * 2 + 1], pa, vb4[2], vb4[3]);
            }
        }
    }

    // ---- epilogue: store fp16 h, [b][t][c]
    const float inv0 = 1.f / l_i0, inv1 = 1.f / l_i1;
    #pragma unroll
    for (int nc = 0; nc < 8; ++nc) {
        const size_t off0 = ((size_t)b * TT + t0 + wid * 16 + g) * CH
                          + head * 64 + nc * 8 + tig * 2;
        __half2 h0 = __floats2half2_rn(oacc[nc][0] * inv0, oacc[nc][1] * inv0);
        *(__half2*)(g_hh + off0) = h0;
        const size_t off1 = off0 + (size_t)8 * CH;
        __half2 h1 = __floats2half2_rn(oacc[nc][2] * inv1, oacc[nc][3] * inv1);
        *(__half2*)(g_hh + off1) = h1;
    }
}

// ---------------- launch ----------------------------------------------------------
extern "C" void kernel_launch(void* const* d_in, const int* in_sizes, int n_in,
                              void* d_out, int out_size) {
    const float* x    = (const float*)d_in[0];
    const float* nw   = (const float*)d_in[1];
    const float* nb   = (const float*)d_in[2];
    const float* qkvw = (const float*)d_in[3];
    const float* qkvb = (const float*)d_in[4];
    const float* pw   = (const float*)d_in[5];
    const float* pb   = (const float*)d_in[6];
    float* out = (float*)d_out;

    const int SM_QKV  = 3 * (2 * GSB * 2);   // 61440
    const int SM_PROJ = 3 * (3 * GSB * 2);   // 92160
    cudaFuncSetAttribute(hgemm_kernel<false>,
                         cudaFuncAttributeMaxDynamicSharedMemorySize, SM_QKV);
    cudaFuncSetAttribute(hgemm_kernel<true>,
                         cudaFuncAttributeMaxDynamicSharedMemorySize, SM_PROJ);
    cudaFuncSetAttribute(attn_kernel,
                         cudaFuncAttributeMaxDynamicSharedMemorySize, ATTN_SMEM);

    gn_stats_kernel<<<BATCH * 32, 256>>>(x);
    w_pack_kernel<<<(3 * CH * CH + CH * CH) / 2 / 256, 256>>>(qkvw, pw);
    x_pack_kernel<<<dim3(16, 8, 16), 256>>>(x, nw, nb);
    hgemm_kernel<false><<<dim3(8, 12, BATCH), 256, SM_QKV>>>(qkvb, nullptr, nullptr);
    attn_kernel<<<dim3(8, NHEAD, BATCH), 256, ATTN_SMEM>>>();
    hgemm_kernel<true><<<dim3(8, 4, BATCH), 256, SM_PROJ>>>(pb, x, out);
}

// round 11
// speedup vs baseline: 5.7193x; 1.0329x over previous
#include <cuda_runtime.h>
#include <cuda_fp16.h>
#include <stdint.h>
#include <math.h>

#define BATCH 16
#define CH    512
#define TT    1024
#define NHEAD 8
#define BHD   (BATCH * NHEAD)
#define HD    64

// ---------------- scratch ----------------------------------------------------
__device__ float g_mean[BATCH * 32];
__device__ float g_rstd[BATCH * 32];
__device__ __half g_Xh[(size_t)BATCH * TT * CH];
__device__ __half g_Whq[3 * CH * CH];
__device__ __half g_Whp[CH * CH];
__device__ __half g_Qh[(size_t)BHD * TT * HD];
__device__ __half g_Kh[(size_t)BHD * TT * HD];
__device__ __half g_Vh[(size_t)BHD * HD * TT];
__device__ __half g_hh[(size_t)BATCH * TT * CH];

// ---------------- helpers ------------------------------------------------------
__device__ __forceinline__ void mma16816(float c[4], const uint32_t a[4],
                                         uint32_t b0, uint32_t b1) {
    asm volatile(
        "mma.sync.aligned.m16n8k16.row.col.f32.f16.f16.f32 "
        "{%0,%1,%2,%3}, {%4,%5,%6,%7}, {%8,%9}, {%0,%1,%2,%3};"
        : "+f"(c[0]), "+f"(c[1]), "+f"(c[2]), "+f"(c[3])
        : "r"(a[0]), "r"(a[1]), "r"(a[2]), "r"(a[3]), "r"(b0), "r"(b1));
}
__device__ __forceinline__ void ldsm4(uint32_t r[4], uint32_t addr) {
    asm volatile("ldmatrix.sync.aligned.m8n8.x4.shared.b16 {%0,%1,%2,%3}, [%4];"
                 : "=r"(r[0]), "=r"(r[1]), "=r"(r[2]), "=r"(r[3]) : "r"(addr));
}
__device__ __forceinline__ uint32_t smem_u32(const void* p) {
    uint32_t a;
    asm("{ .reg .u64 t; cvta.to.shared.u64 t, %1; cvt.u32.u64 %0, t; }"
        : "=r"(a) : "l"(p));
    return a;
}
__device__ __forceinline__ void cp16(uint32_t d, const void* s) {
    asm volatile("cp.async.cg.shared.global [%0], [%1], 16;" :: "r"(d), "l"(s));
}
#define CP_COMMIT() asm volatile("cp.async.commit_group;" ::: "memory")
#define CP_WAIT(n)  asm volatile("cp.async.wait_group %0;" :: "n"(n) : "memory")

// ---------------- init: GroupNorm stats (blocks 0..511) + weight fp16 pack ------
__global__ void init_pack_kernel(const float* __restrict__ x,
                                 const float* __restrict__ qw,
                                 const float* __restrict__ pw) {
    if (blockIdx.x < 512) {
        const int bg = blockIdx.x;
        const float4* base = (const float4*)(x + (size_t)bg * 16 * TT);
        float s = 0.f, ss = 0.f;
        for (int i = threadIdx.x; i < 4096; i += 256) {
            float4 v = base[i];
            s  += v.x + v.y + v.z + v.w;
            ss += v.x*v.x + v.y*v.y + v.z*v.z + v.w*v.w;
        }
        #pragma unroll
        for (int o = 16; o; o >>= 1) {
            s  += __shfl_down_sync(0xffffffffu, s,  o);
            ss += __shfl_down_sync(0xffffffffu, ss, o);
        }
        __shared__ float sh[16];
        const int w = threadIdx.x >> 5, l = threadIdx.x & 31;
        if (l == 0) { sh[w] = s; sh[8 + w] = ss; }
        __syncthreads();
        if (threadIdx.x == 0) {
            float S = 0.f, SS = 0.f;
            #pragma unroll
            for (int i = 0; i < 8; i++) { S += sh[i]; SS += sh[8 + i]; }
            const float mean = S * (1.f / 16384.f);
            const float var  = SS * (1.f / 16384.f) - mean * mean;
            g_mean[bg] = mean;
            g_rstd[bg] = rsqrtf(var + 1e-5f);
        }
    } else {
        const int i = (blockIdx.x - 512) * 256 + threadIdx.x;   // pair index
        const int NQ = 3 * CH * CH / 2;
        if (i < NQ) {
            float2 v = ((const float2*)qw)[i];
            __half2 h = __floats2half2_rn(v.x, v.y);
            ((uint32_t*)g_Whq)[i] = *(uint32_t*)&h;
        } else {
            const int j = i - NQ;
            float2 v = ((const float2*)pw)[j];
            __half2 h = __floats2half2_rn(v.x, v.y);
            ((uint32_t*)g_Whp)[j] = *(uint32_t*)&h;
        }
    }
}

// ---------------- x pack: GroupNorm + fp16 + transpose -> [b][t][c] -------------
__global__ void x_pack_kernel(const float* __restrict__ x,
                              const float* __restrict__ nw,
                              const float* __restrict__ nb) {
    __shared__ float tile[64][68];
    const int t0 = blockIdx.x * 64, c0 = blockIdx.y * 64, b = blockIdx.z;
    const int tid = threadIdx.x;
    const float* xb = x + (size_t)b * CH * TT;
    #pragma unroll
    for (int it = 0; it < 4; ++it) {
        const int f = tid + it * 256;
        const int cl = f >> 4, t4 = (f & 15) << 2;
        const int c = c0 + cl;
        float4 v = *(const float4*)(xb + (size_t)c * TT + t0 + t4);
        const int bg = (b << 5) + (c >> 4);
        const float w  = nw[c] * g_rstd[bg];
        const float bb = fmaf(-g_mean[bg], w, nb[c]);
        tile[cl][t4 + 0] = fmaf(v.x, w, bb);
        tile[cl][t4 + 1] = fmaf(v.y, w, bb);
        tile[cl][t4 + 2] = fmaf(v.z, w, bb);
        tile[cl][t4 + 3] = fmaf(v.w, w, bb);
    }
    __syncthreads();
    #pragma unroll
    for (int it = 0; it < 4; ++it) {
        const int f = tid + it * 256;
        const int tl = f >> 4, c4 = (f & 15) << 2;
        __half2 h0 = __floats2half2_rn(tile[c4 + 0][tl], tile[c4 + 1][tl]);
        __half2 h1 = __floats2half2_rn(tile[c4 + 2][tl], tile[c4 + 3][tl]);
        const size_t off = ((size_t)b * TT + t0 + tl) * CH + c0 + c4;
        *(uint2*)(g_Xh + off) = make_uint2(*(uint32_t*)&h0, *(uint32_t*)&h1);
    }
}

// ---------------- HMMA GEMM (1-term), 4-stage cp.async ring ----------------------
// qkv (IS_PROJ=0): A = Xh rows t, B = Whq rows m; frag = [t][m]; packs Q/K/V.
// proj (IS_PROJ=1): A = Whp rows m, B = hh rows t; frag = [m][t]; fp32 out + resid.
#define GP 40
#define GSB (128 * GP)                   // 5120 halves per array
#define GSTG (2 * GSB * 2)               // 20480 B per stage
#define GEMM_SMEM (4 * GSTG)             // 81920 B

template<bool IS_PROJ>
__global__ __launch_bounds__(256, 2)
void hgemm_kernel(const float* __restrict__ bias,
                  const float* __restrict__ resid,
                  float* __restrict__ outp) {
    extern __shared__ __half smh[];
    const uint32_t sb = smem_u32(smh);
    const int tid = threadIdx.x, lane = tid & 31, wid = tid >> 5;
    const int g = lane >> 2, tig = lane & 3;
    const int b = blockIdx.z;
    const int r0 = (IS_PROJ ? blockIdx.y : blockIdx.x) * 128;
    const int c0 = (IS_PROJ ? blockIdx.x : blockIdx.y) * 128;
    const int warp_m = wid >> 2, warp_n = wid & 3;

    const __half *pAh, *pBh;
    if (IS_PROJ) {
        pAh = g_Whp + (size_t)r0 * CH;
        pBh = g_hh + ((size_t)b * TT + c0) * CH;
    } else {
        pAh = g_Xh + ((size_t)b * TT + r0) * CH;
        pBh = g_Whq + (size_t)c0 * CH;
    }

    float acc[4][4][4];
    #pragma unroll
    for (int mi = 0; mi < 4; ++mi)
        #pragma unroll
        for (int ni = 0; ni < 4; ++ni)
            #pragma unroll
            for (int r = 0; r < 4; ++r) acc[mi][ni][r] = 0.f;

    const int aRow = warp_m * 64 + (lane & 15);
    const int aK   = (lane >> 4) << 3;
    const int bRow = warp_n * 32 + (lane & 7) + ((lane >> 4) << 3);
    const int bK   = ((lane >> 3) & 1) << 3;

    auto issue = [&](int ck) {
        const uint32_t st = sb + (ck & 3) * GSTG;
        const int k0 = ck * 32;
        #pragma unroll
        for (int it = 0; it < 2; ++it) {
            const int f = tid + it * 256;
            const int row = f >> 2, sg = (f & 3) << 3;
            const uint32_t da = st + (row * GP + sg) * 2;
            cp16(da,           pAh + (size_t)row * CH + k0 + sg);
            cp16(da + GSB * 2, pBh + (size_t)row * CH + k0 + sg);
        }
    };

    auto compute = [&](int ck) {
        const uint32_t st = sb + (ck & 3) * GSTG;
        const uint32_t aH = st, bH = st + GSB * 2;
        #pragma unroll
        for (int kk = 0; kk < 32; kk += 16) {
            uint32_t afh[4][4];
            #pragma unroll
            for (int mi = 0; mi < 4; ++mi)
                ldsm4(afh[mi], aH + ((aRow + mi * 16) * GP + kk + aK) * 2);
            #pragma unroll
            for (int nj = 0; nj < 2; ++nj) {
                uint32_t bfh[4];
                ldsm4(bfh, bH + ((bRow + nj * 16) * GP + kk + bK) * 2);
                #pragma unroll
                for (int mi = 0; mi < 4; ++mi) {
                    mma16816(acc[mi][nj * 2 + 0], afh[mi], bfh[0], bfh[1]);
                    mma16816(acc[mi][nj * 2 + 1], afh[mi], bfh[2], bfh[3]);
                }
            }
        }
    };

    issue(0); CP_COMMIT();
    issue(1); CP_COMMIT();
    issue(2); CP_COMMIT();
    for (int ck = 0; ck < 16; ++ck) {
        if (ck <= 13) CP_WAIT(2);
        else if (ck == 14) CP_WAIT(1);
        else CP_WAIT(0);
        __syncthreads();
        if (ck < 13) { issue(ck + 3); CP_COMMIT(); }
        compute(ck);
    }

    if (IS_PROJ) {
        const int mbase = r0 + warp_m * 64;
        const int nbase = c0 + warp_n * 32;
        const float* xres = resid + (size_t)b * CH * TT;
        float* ob = outp + (size_t)b * CH * TT;
        #pragma unroll
        for (int mi = 0; mi < 4; ++mi) {
            const int mA = mbase + mi * 16 + g;
            const int mB = mA + 8;
            const float biA = bias[mA], biB = bias[mB];
            #pragma unroll
            for (int ni = 0; ni < 4; ++ni) {
                const int t = nbase + ni * 8 + tig * 2;
                float2 v0, v1;
                v0.x = acc[mi][ni][0] + biA; v0.y = acc[mi][ni][1] + biA;
                v1.x = acc[mi][ni][2] + biB; v1.y = acc[mi][ni][3] + biB;
                float2 r0v = *(const float2*)(xres + (size_t)mA * TT + t);
                float2 r1v = *(const float2*)(xres + (size_t)mB * TT + t);
                v0.x += r0v.x; v0.y += r0v.y;
                v1.x += r1v.x; v1.y += r1v.y;
                *(float2*)(ob + (size_t)mA * TT + t) = v0;
                *(float2*)(ob + (size_t)mB * TT + t) = v1;
            }
        }
    } else {
        #pragma unroll
        for (int ni = 0; ni < 4; ++ni) {
            const int m = c0 + warp_n * 32 + ni * 8 + tig * 2;
            const int head = m / 192;
            const int rmod = m - head * 192;
            const int kind = rmod >> 6, c = rmod & 63;
            const int bh = b * NHEAD + head;
            const float b0v = bias[m], b1v = bias[m + 1];
            #pragma unroll
            for (int mi = 0; mi < 4; ++mi) {
                #pragma unroll
                for (int rr = 0; rr < 2; ++rr) {
                    const int t = r0 + warp_m * 64 + mi * 16 + g + rr * 8;
                    const float v0 = acc[mi][ni][rr * 2 + 0] + b0v;
                    const float v1 = acc[mi][ni][rr * 2 + 1] + b1v;
                    if (kind == 0) {
                        __half2 h2 = __floats2half2_rn(v0, v1);
                        *(__half2*)(g_Qh + ((size_t)bh * TT + t) * HD + c) = h2;
                    } else if (kind == 1) {
                        __half2 h2 = __floats2half2_rn(v0, v1);
                        *(__half2*)(g_Kh + ((size_t)bh * TT + t) * HD + c) = h2;
                    } else {
                        g_Vh[((size_t)bh * HD + c) * TT + t]     = __float2half_rn(v0);
                        g_Vh[((size_t)bh * HD + c + 1) * TT + t] = __float2half_rn(v1);
                    }
                }
            }
        }
    }
}

// ---------------- HMMA flash attention (1-term QK, 1-term PV), 4-stage ring -----
// smem halves: Qh @0 (128x72); stage k @9216+(k&3)*9216: Kh +0, Vh +4608.
#define AP 72
#define ATTN_SMEM ((9216 + 4 * 9216) * 2)   // 92160 B

__global__ __launch_bounds__(256)
void attn_kernel() {
    extern __shared__ __half sa[];
    const uint32_t sb = smem_u32(sa);
    const int tid = threadIdx.x, lane = tid & 31, wid = tid >> 5;
    const int g = lane >> 2, tig = lane & 3;
    const int tblk = blockIdx.x, head = blockIdx.y, b = blockIdx.z;
    const int bh = b * NHEAD + head;
    const int t0 = tblk * 128;

    {   // Q: 128 rows x 64 halves (part of group 0)
        const __half* qh = g_Qh + ((size_t)bh * TT + t0) * HD;
        #pragma unroll
        for (int it = 0; it < 4; ++it) {
            const int f = tid + it * 256;
            const int row = f >> 3, sg = (f & 7) << 3;
            cp16(sb + (row * AP + sg) * 2, qh + (size_t)row * HD + sg);
        }
    }
    auto issueKV = [&](int kb) {
        const uint32_t st = sb + (9216 + (kb & 3) * 9216) * 2;
        const int s0 = kb * 64;
        const __half* kh = g_Kh + ((size_t)bh * TT + s0) * HD;
        const __half* vh = g_Vh + (size_t)bh * HD * TT + s0;
        #pragma unroll
        for (int it = 0; it < 2; ++it) {
            const int f = tid + it * 256;
            const int row = f >> 3, sg = (f & 7) << 3;
            cp16(st + (row * AP + sg) * 2,        kh + (size_t)row * HD + sg);
            cp16(st + (4608 + row * AP + sg) * 2, vh + (size_t)row * TT + sg);
        }
    };

    issueKV(0); CP_COMMIT();
    issueKV(1); CP_COMMIT();
    issueKV(2); CP_COMMIT();

    const int qRow = wid * 16 + (lane & 15);
    const int qK   = (lane >> 4) << 3;
    const int nRow = (lane & 7) + ((lane >> 4) << 3);
    const int nK   = ((lane >> 3) & 1) << 3;

    float m_i0 = -1e30f, m_i1 = -1e30f, l_i0 = 0.f, l_i1 = 0.f;
    float oacc[8][4];
    #pragma unroll
    for (int nc = 0; nc < 8; ++nc)
        #pragma unroll
        for (int r = 0; r < 4; ++r) oacc[nc][r] = 0.f;

    for (int kb = 0; kb < 16; ++kb) {
        if (kb <= 13) CP_WAIT(2);
        else if (kb == 14) CP_WAIT(1);
        else CP_WAIT(0);
        __syncthreads();
        if (kb < 13) { issueKV(kb + 3); CP_COMMIT(); }
        const uint32_t st = sb + (9216 + (kb & 3) * 9216) * 2;

        // ---- S = Qh Kh^T
        float sacc[8][4];
        #pragma unroll
        for (int ni = 0; ni < 8; ++ni)
            #pragma unroll
            for (int r = 0; r < 4; ++r) sacc[ni][r] = 0.f;

        #pragma unroll
        for (int ks = 0; ks < 4; ++ks) {
            uint32_t ah[4];
            ldsm4(ah, sb + ((qRow * AP) + ks * 16 + qK) * 2);
            #pragma unroll
            for (int nj = 0; nj < 4; ++nj) {
                uint32_t kb4[4];
                ldsm4(kb4, st + (((nj * 16 + nRow) * AP) + ks * 16 + nK) * 2);
                mma16816(sacc[nj * 2 + 0], ah, kb4[0], kb4[1]);
                mma16816(sacc[nj * 2 + 1], ah, kb4[2], kb4[3]);
            }
        }
        #pragma unroll
        for (int ni = 0; ni < 8; ++ni)
            #pragma unroll
            for (int r = 0; r < 4; ++r) sacc[ni][r] *= 0.125f;

        // ---- online softmax (rows g and g+8)
        float mx0 = -1e30f, mx1 = -1e30f;
        #pragma unroll
        for (int ni = 0; ni < 8; ++ni) {
            mx0 = fmaxf(mx0, fmaxf(sacc[ni][0], sacc[ni][1]));
            mx1 = fmaxf(mx1, fmaxf(sacc[ni][2], sacc[ni][3]));
        }
        mx0 = fmaxf(mx0, __shfl_xor_sync(0xffffffffu, mx0, 1));
        mx0 = fmaxf(mx0, __shfl_xor_sync(0xffffffffu, mx0, 2));
        mx1 = fmaxf(mx1, __shfl_xor_sync(0xffffffffu, mx1, 1));
        mx1 = fmaxf(mx1, __shfl_xor_sync(0xffffffffu, mx1, 2));
        const float mn0 = fmaxf(m_i0, mx0), mn1 = fmaxf(m_i1, mx1);
        const float c0 = __expf(m_i0 - mn0), c1 = __expf(m_i1 - mn1);
        m_i0 = mn0; m_i1 = mn1;
        float rs0 = 0.f, rs1 = 0.f;
        uint32_t pfrag[8][2];
        #pragma unroll
        for (int ni = 0; ni < 8; ++ni) {
            const float p0 = __expf(sacc[ni][0] - mn0);
            const float p1 = __expf(sacc[ni][1] - mn0);
            const float p2 = __expf(sacc[ni][2] - mn1);
            const float p3 = __expf(sacc[ni][3] - mn1);
            rs0 += p0 + p1; rs1 += p2 + p3;
            __half2 h0 = __floats2half2_rn(p0, p1);
            __half2 h1 = __floats2half2_rn(p2, p3);
            pfrag[ni][0] = *reinterpret_cast<uint32_t*>(&h0);
            pfrag[ni][1] = *reinterpret_cast<uint32_t*>(&h1);
        }
        rs0 += __shfl_xor_sync(0xffffffffu, rs0, 1);
        rs0 += __shfl_xor_sync(0xffffffffu, rs0, 2);
        rs1 += __shfl_xor_sync(0xffffffffu, rs1, 1);
        rs1 += __shfl_xor_sync(0xffffffffu, rs1, 2);
        l_i0 = l_i0 * c0 + rs0;
        l_i1 = l_i1 * c1 + rs1;
        #pragma unroll
        for (int nc = 0; nc < 8; ++nc) {
            oacc[nc][0] *= c0; oacc[nc][1] *= c0;
            oacc[nc][2] *= c1; oacc[nc][3] *= c1;
        }

        // ---- O += P Vh^T
        #pragma unroll
        for (int ks = 0; ks < 4; ++ks) {
            const uint32_t pa[4] = { pfrag[2 * ks][0], pfrag[2 * ks][1],
                                     pfrag[2 * ks + 1][0], pfrag[2 * ks + 1][1] };
            #pragma unroll
            for (int nj = 0; nj < 4; ++nj) {
                uint32_t vb4[4];
                ldsm4(vb4, st + ((4608 + (nj * 16 + nRow) * AP) + ks * 16 + nK) * 2);
                mma16816(oacc[nj * 2 + 0], pa, vb4[0], vb4[1]);
                mma16816(oacc[nj * 2 + 1], pa, vb4[2], vb4[3]);
            }
        }
    }

    // ---- epilogue: store fp16 h, [b][t][c]
    const float inv0 = 1.f / l_i0, inv1 = 1.f / l_i1;
    #pragma unroll
    for (int nc = 0; nc < 8; ++nc) {
        const size_t off0 = ((size_t)b * TT + t0 + wid * 16 + g) * CH
                          + head * 64 + nc * 8 + tig * 2;
        __half2 h0 = __floats2half2_rn(oacc[nc][0] * inv0, oacc[nc][1] * inv0);
        *(__half2*)(g_hh + off0) = h0;
        const size_t off1 = off0 + (size_t)8 * CH;
        __half2 h1 = __floats2half2_rn(oacc[nc][2] * inv1, oacc[nc][3] * inv1);
        *(__half2*)(g_hh + off1) = h1;
    }
}

// ---------------- launch ----------------------------------------------------------
extern "C" void kernel_launch(void* const* d_in, const int* in_sizes, int n_in,
                              void* d_out, int out_size) {
    const float* x    = (const float*)d_in[0];
    const float* nw   = (const float*)d_in[1];
    const float* nb   = (const float*)d_in[2];
    const float* qkvw = (const float*)d_in[3];
    const float* qkvb = (const float*)d_in[4];
    const float* pw   = (const float*)d_in[5];
    const float* pb   = (const float*)d_in[6];
    float* out = (float*)d_out;

    cudaFuncSetAttribute(hgemm_kernel<false>,
                         cudaFuncAttributeMaxDynamicSharedMemorySize, GEMM_SMEM);
    cudaFuncSetAttribute(hgemm_kernel<true>,
                         cudaFuncAttributeMaxDynamicSharedMemorySize, GEMM_SMEM);
    cudaFuncSetAttribute(attn_kernel,
                         cudaFuncAttributeMaxDynamicSharedMemorySize, ATTN_SMEM);

    // blocks 0..511: GroupNorm stats; 512..2559: weight pack (4*CH*CH/2/256 = 2048)
    init_pack_kernel<<<512 + 2048, 256>>>(x, qkvw, pw);
    x_pack_kernel<<<dim3(16, 8, 16), 256>>>(x, nw, nb);
    hgemm_kernel<false><<<dim3(8, 12, BATCH), 256, GEMM_SMEM>>>(qkvb, nullptr, nullptr);
    attn_kernel<<<dim3(8, NHEAD, BATCH), 256, ATTN_SMEM>>>();
    hgemm_kernel<true><<<dim3(8, 4, BATCH), 256, GEMM_SMEM>>>(pb, x, out);
}

// round 13
// speedup vs baseline: 5.9549x; 1.0412x over previous
#include <cuda_runtime.h>
#include <cuda_fp16.h>
#include <stdint.h>
#include <math.h>

#define BATCH 16
#define CH    512
#define TT    1024
#define NHEAD 8
#define BHD   (BATCH * NHEAD)
#define HD    64

// Q pre-scale: hd^-0.5 (=0.125) * log2(e), so softmax runs in exp2 domain
#define QSCALE 0.1803368801111f

// ---------------- scratch ----------------------------------------------------
__device__ float g_mean[BATCH * 32];
__device__ float g_rstd[BATCH * 32];
__device__ __half g_Xh[(size_t)BATCH * TT * CH];
__device__ __half g_Whq[3 * CH * CH];
__device__ __half g_Whp[CH * CH];
__device__ __half g_Qh[(size_t)BHD * TT * HD];
__device__ __half g_Kh[(size_t)BHD * TT * HD];
__device__ __half g_Vh[(size_t)BHD * HD * TT];
__device__ __half g_hh[(size_t)BATCH * TT * CH];

// ---------------- helpers ------------------------------------------------------
__device__ __forceinline__ float ex2(float x) {
    float y;
    asm("ex2.approx.ftz.f32 %0, %1;" : "=f"(y) : "f"(x));
    return y;
}
__device__ __forceinline__ void mma16816(float c[4], const uint32_t a[4],
                                         uint32_t b0, uint32_t b1) {
    asm volatile(
        "mma.sync.aligned.m16n8k16.row.col.f32.f16.f16.f32 "
        "{%0,%1,%2,%3}, {%4,%5,%6,%7}, {%8,%9}, {%0,%1,%2,%3};"
        : "+f"(c[0]), "+f"(c[1]), "+f"(c[2]), "+f"(c[3])
        : "r"(a[0]), "r"(a[1]), "r"(a[2]), "r"(a[3]), "r"(b0), "r"(b1));
}
__device__ __forceinline__ void ldsm4(uint32_t r[4], uint32_t addr) {
    asm volatile("ldmatrix.sync.aligned.m8n8.x4.shared.b16 {%0,%1,%2,%3}, [%4];"
                 : "=r"(r[0]), "=r"(r[1]), "=r"(r[2]), "=r"(r[3]) : "r"(addr));
}
__device__ __forceinline__ uint32_t smem_u32(const void* p) {
    uint32_t a;
    asm("{ .reg .u64 t; cvta.to.shared.u64 t, %1; cvt.u32.u64 %0, t; }"
        : "=r"(a) : "l"(p));
    return a;
}
__device__ __forceinline__ void cp16(uint32_t d, const void* s) {
    asm volatile("cp.async.cg.shared.global [%0], [%1], 16;" :: "r"(d), "l"(s));
}
#define CP_COMMIT() asm volatile("cp.async.commit_group;" ::: "memory")
#define CP_WAIT(n)  asm volatile("cp.async.wait_group %0;" :: "n"(n) : "memory")

// ---------------- init: GroupNorm stats (blocks 0..511) + weight fp16 pack ------
__global__ void init_pack_kernel(const float* __restrict__ x,
                                 const float* __restrict__ qw,
                                 const float* __restrict__ pw) {
    if (blockIdx.x < 512) {
        const int bg = blockIdx.x;
        const float4* base = (const float4*)(x + (size_t)bg * 16 * TT);
        float s = 0.f, ss = 0.f;
        for (int i = threadIdx.x; i < 4096; i += 256) {
            float4 v = base[i];
            s  += v.x + v.y + v.z + v.w;
            ss += v.x*v.x + v.y*v.y + v.z*v.z + v.w*v.w;
        }
        #pragma unroll
        for (int o = 16; o; o >>= 1) {
            s  += __shfl_down_sync(0xffffffffu, s,  o);
            ss += __shfl_down_sync(0xffffffffu, ss, o);
        }
        __shared__ float sh[16];
        const int w = threadIdx.x >> 5, l = threadIdx.x & 31;
        if (l == 0) { sh[w] = s; sh[8 + w] = ss; }
        __syncthreads();
        if (threadIdx.x == 0) {
            float S = 0.f, SS = 0.f;
            #pragma unroll
            for (int i = 0; i < 8; i++) { S += sh[i]; SS += sh[8 + i]; }
            const float mean = S * (1.f / 16384.f);
            const float var  = SS * (1.f / 16384.f) - mean * mean;
            g_mean[bg] = mean;
            g_rstd[bg] = rsqrtf(var + 1e-5f);
        }
    } else {
        const int i = (blockIdx.x - 512) * 256 + threadIdx.x;
        const int NQ = 3 * CH * CH / 2;
        if (i < NQ) {
            float2 v = ((const float2*)qw)[i];
            __half2 h = __floats2half2_rn(v.x, v.y);
            ((uint32_t*)g_Whq)[i] = *(uint32_t*)&h;
        } else {
            const int j = i - NQ;
            float2 v = ((const float2*)pw)[j];
            __half2 h = __floats2half2_rn(v.x, v.y);
            ((uint32_t*)g_Whp)[j] = *(uint32_t*)&h;
        }
    }
}

// ---------------- x pack: GroupNorm + fp16 + transpose -> [b][t][c] -------------
__global__ void x_pack_kernel(const float* __restrict__ x,
                              const float* __restrict__ nw,
                              const float* __restrict__ nb) {
    __shared__ float tile[64][68];
    const int t0 = blockIdx.x * 64, c0 = blockIdx.y * 64, b = blockIdx.z;
    const int tid = threadIdx.x;
    const float* xb = x + (size_t)b * CH * TT;
    #pragma unroll
    for (int it = 0; it < 4; ++it) {
        const int f = tid + it * 256;
        const int cl = f >> 4, t4 = (f & 15) << 2;
        const int c = c0 + cl;
        float4 v = *(const float4*)(xb + (size_t)c * TT + t0 + t4);
        const int bg = (b << 5) + (c >> 4);
        const float w  = nw[c] * g_rstd[bg];
        const float bb = fmaf(-g_mean[bg], w, nb[c]);
        tile[cl][t4 + 0] = fmaf(v.x, w, bb);
        tile[cl][t4 + 1] = fmaf(v.y, w, bb);
        tile[cl][t4 + 2] = fmaf(v.z, w, bb);
        tile[cl][t4 + 3] = fmaf(v.w, w, bb);
    }
    __syncthreads();
    #pragma unroll
    for (int it = 0; it < 4; ++it) {
        const int f = tid + it * 256;
        const int tl = f >> 4, c4 = (f & 15) << 2;
        __half2 h0 = __floats2half2_rn(tile[c4 + 0][tl], tile[c4 + 1][tl]);
        __half2 h1 = __floats2half2_rn(tile[c4 + 2][tl], tile[c4 + 3][tl]);
        const size_t off = ((size_t)b * TT + t0 + tl) * CH + c0 + c4;
        *(uint2*)(g_Xh + off) = make_uint2(*(uint32_t*)&h0, *(uint32_t*)&h1);
    }
}

// ---------------- HMMA GEMM (1-term), 4-stage cp.async ring ----------------------
#define GP 40
#define GSB (128 * GP)
#define GSTG (2 * GSB * 2)
#define GEMM_SMEM (4 * GSTG)

template<bool IS_PROJ>
__global__ __launch_bounds__(256, 2)
void hgemm_kernel(const float* __restrict__ bias,
                  const float* __restrict__ resid,
                  float* __restrict__ outp) {
    extern __shared__ __half smh[];
    const uint32_t sb = smem_u32(smh);
    const int tid = threadIdx.x, lane = tid & 31, wid = tid >> 5;
    const int g = lane >> 2, tig = lane & 3;
    const int b = blockIdx.z;
    const int r0 = (IS_PROJ ? blockIdx.y : blockIdx.x) * 128;
    const int c0 = (IS_PROJ ? blockIdx.x : blockIdx.y) * 128;
    const int warp_m = wid >> 2, warp_n = wid & 3;

    const __half *pAh, *pBh;
    if (IS_PROJ) {
        pAh = g_Whp + (size_t)r0 * CH;
        pBh = g_hh + ((size_t)b * TT + c0) * CH;
    } else {
        pAh = g_Xh + ((size_t)b * TT + r0) * CH;
        pBh = g_Whq + (size_t)c0 * CH;
    }

    float acc[4][4][4];
    #pragma unroll
    for (int mi = 0; mi < 4; ++mi)
        #pragma unroll
        for (int ni = 0; ni < 4; ++ni)
            #pragma unroll
            for (int r = 0; r < 4; ++r) acc[mi][ni][r] = 0.f;

    const int aRow = warp_m * 64 + (lane & 15);
    const int aK   = (lane >> 4) << 3;
    const int bRow = warp_n * 32 + (lane & 7) + ((lane >> 4) << 3);
    const int bK   = ((lane >> 3) & 1) << 3;

    auto issue = [&](int ck) {
        const uint32_t st = sb + (ck & 3) * GSTG;
        const int k0 = ck * 32;
        #pragma unroll
        for (int it = 0; it < 2; ++it) {
            const int f = tid + it * 256;
            const int row = f >> 2, sg = (f & 3) << 3;
            const uint32_t da = st + (row * GP + sg) * 2;
            cp16(da,           pAh + (size_t)row * CH + k0 + sg);
            cp16(da + GSB * 2, pBh + (size_t)row * CH + k0 + sg);
        }
    };

    auto compute = [&](int ck) {
        const uint32_t st = sb + (ck & 3) * GSTG;
        const uint32_t aH = st, bH = st + GSB * 2;
        #pragma unroll
        for (int kk = 0; kk < 32; kk += 16) {
            uint32_t afh[4][4];
            #pragma unroll
            for (int mi = 0; mi < 4; ++mi)
                ldsm4(afh[mi], aH + ((aRow + mi * 16) * GP + kk + aK) * 2);
            #pragma unroll
            for (int nj = 0; nj < 2; ++nj) {
                uint32_t bfh[4];
                ldsm4(bfh, bH + ((bRow + nj * 16) * GP + kk + bK) * 2);
                #pragma unroll
                for (int mi = 0; mi < 4; ++mi) {
                    mma16816(acc[mi][nj * 2 + 0], afh[mi], bfh[0], bfh[1]);
                    mma16816(acc[mi][nj * 2 + 1], afh[mi], bfh[2], bfh[3]);
                }
            }
        }
    };

    issue(0); CP_COMMIT();
    issue(1); CP_COMMIT();
    issue(2); CP_COMMIT();
    for (int ck = 0; ck < 16; ++ck) {
        if (ck <= 13) CP_WAIT(2);
        else if (ck == 14) CP_WAIT(1);
        else CP_WAIT(0);
        __syncthreads();
        if (ck < 13) { issue(ck + 3); CP_COMMIT(); }
        compute(ck);
    }

    if (IS_PROJ) {
        const int mbase = r0 + warp_m * 64;
        const int nbase = c0 + warp_n * 32;
        const float* xres = resid + (size_t)b * CH * TT;
        float* ob = outp + (size_t)b * CH * TT;
        #pragma unroll
        for (int mi = 0; mi < 4; ++mi) {
            const int mA = mbase + mi * 16 + g;
            const int mB = mA + 8;
            const float biA = bias[mA], biB = bias[mB];
            #pragma unroll
            for (int ni = 0; ni < 4; ++ni) {
                const int t = nbase + ni * 8 + tig * 2;
                float2 v0, v1;
                v0.x = acc[mi][ni][0] + biA; v0.y = acc[mi][ni][1] + biA;
                v1.x = acc[mi][ni][2] + biB; v1.y = acc[mi][ni][3] + biB;
                float2 r0v = *(const float2*)(xres + (size_t)mA * TT + t);
                float2 r1v = *(const float2*)(xres + (size_t)mB * TT + t);
                v0.x += r0v.x; v0.y += r0v.y;
                v1.x += r1v.x; v1.y += r1v.y;
                *(float2*)(ob + (size_t)mA * TT + t) = v0;
                *(float2*)(ob + (size_t)mB * TT + t) = v1;
            }
        }
    } else {
        #pragma unroll
        for (int ni = 0; ni < 4; ++ni) {
            const int m = c0 + warp_n * 32 + ni * 8 + tig * 2;
            const int head = m / 192;
            const int rmod = m - head * 192;
            const int kind = rmod >> 6, c = rmod & 63;
            const int bh = b * NHEAD + head;
            const float b0v = bias[m], b1v = bias[m + 1];
            #pragma unroll
            for (int mi = 0; mi < 4; ++mi) {
                #pragma unroll
                for (int rr = 0; rr < 2; ++rr) {
                    const int t = r0 + warp_m * 64 + mi * 16 + g + rr * 8;
                    float v0 = acc[mi][ni][rr * 2 + 0] + b0v;
                    float v1 = acc[mi][ni][rr * 2 + 1] + b1v;
                    if (kind == 0) {
                        v0 *= QSCALE; v1 *= QSCALE;   // fold softmax scale + log2e
                        __half2 h2 = __floats2half2_rn(v0, v1);
                        *(__half2*)(g_Qh + ((size_t)bh * TT + t) * HD + c) = h2;
                    } else if (kind == 1) {
                        __half2 h2 = __floats2half2_rn(v0, v1);
                        *(__half2*)(g_Kh + ((size_t)bh * TT + t) * HD + c) = h2;
                    } else {
                        g_Vh[((size_t)bh * HD + c) * TT + t]     = __float2half_rn(v0);
                        g_Vh[((size_t)bh * HD + c + 1) * TT + t] = __float2half_rn(v1);
                    }
                }
            }
        }
    }
}

// ---------------- HMMA flash attention: KV block 128, 2-stage ring, exp2 domain --
// smem halves: Q @0 (128 x AP); stage s @9216 + s*17920: K 128xAP (+0),
//              V 64 x VP (+9216). AP=72, VP=136.
// Ring discipline (2 stages): compute(kb) -> __syncthreads -> issue(kb+2);
// issuing before compute would overwrite the stage being read (R12 bug).
#define AP 72
#define VP 136
#define ASTG (9216 + 8704)                  // 17920 halves per stage
#define ATTN_SMEM ((9216 + 2 * ASTG) * 2)   // 90112 B

__global__ __launch_bounds__(256, 2)
void attn_kernel() {
    extern __shared__ __half sa[];
    const uint32_t sb = smem_u32(sa);
    const int tid = threadIdx.x, lane = tid & 31, wid = tid >> 5;
    const int g = lane >> 2, tig = lane & 3;
    const int tblk = blockIdx.x, head = blockIdx.y, b = blockIdx.z;
    const int bh = b * NHEAD + head;
    const int t0 = tblk * 128;

    {   // Q: 128 rows x 64 halves (group 0)
        const __half* qh = g_Qh + ((size_t)bh * TT + t0) * HD;
        #pragma unroll
        for (int it = 0; it < 4; ++it) {
            const int f = tid + it * 256;
            const int row = f >> 3, sg = (f & 7) << 3;
            cp16(sb + (row * AP + sg) * 2, qh + (size_t)row * HD + sg);
        }
    }
    auto issueKV = [&](int kb) {
        const uint32_t st = sb + (9216 + (kb & 1) * ASTG) * 2;
        const int s0 = kb * 128;
        const __half* kh = g_Kh + ((size_t)bh * TT + s0) * HD;
        const __half* vh = g_Vh + (size_t)bh * HD * TT + s0;
        #pragma unroll
        for (int it = 0; it < 4; ++it) {
            const int f = tid + it * 256;
            const int kr = f >> 3, ksg = (f & 7) << 3;        // K: 128 rows x 64
            cp16(st + (kr * AP + ksg) * 2, kh + (size_t)kr * HD + ksg);
            const int vr = f >> 4, vsg = (f & 15) << 3;       // V: 64 rows x 128
            cp16(st + (9216 + vr * VP + vsg) * 2, vh + (size_t)vr * TT + vsg);
        }
    };

    issueKV(0); CP_COMMIT();
    issueKV(1); CP_COMMIT();

    const int qRow = wid * 16 + (lane & 15);
    const int qK   = (lane >> 4) << 3;
    const int nRow = (lane & 7) + ((lane >> 4) << 3);
    const int nK   = ((lane >> 3) & 1) << 3;

    float m_i0 = -1e30f, m_i1 = -1e30f, l_i0 = 0.f, l_i1 = 0.f;
    float oacc[8][4];
    #pragma unroll
    for (int nc = 0; nc < 8; ++nc)
        #pragma unroll
        for (int r = 0; r < 4; ++r) oacc[nc][r] = 0.f;

    for (int kb = 0; kb < 8; ++kb) {
        if (kb < 7) CP_WAIT(1); else CP_WAIT(0);
        __syncthreads();
        const uint32_t st = sb + (9216 + (kb & 1) * ASTG) * 2;

        // ---- S = Q K^T over 128 s-cols (Q pre-scaled into exp2 domain)
        float sacc[16][4];
        #pragma unroll
        for (int ni = 0; ni < 16; ++ni)
            #pragma unroll
            for (int r = 0; r < 4; ++r) sacc[ni][r] = 0.f;

        #pragma unroll
        for (int ks = 0; ks < 4; ++ks) {
            uint32_t ah[4];
            ldsm4(ah, sb + ((qRow * AP) + ks * 16 + qK) * 2);
            #pragma unroll
            for (int nj = 0; nj < 8; ++nj) {
                uint32_t kb4[4];
                ldsm4(kb4, st + (((nj * 16 + nRow) * AP) + ks * 16 + nK) * 2);
                mma16816(sacc[nj * 2 + 0], ah, kb4[0], kb4[1]);
                mma16816(sacc[nj * 2 + 1], ah, kb4[2], kb4[3]);
            }
        }

        // ---- online softmax in exp2 domain (rows g and g+8)
        float mx0 = -1e30f, mx1 = -1e30f;
        #pragma unroll
        for (int ni = 0; ni < 16; ++ni) {
            mx0 = fmaxf(mx0, fmaxf(sacc[ni][0], sacc[ni][1]));
            mx1 = fmaxf(mx1, fmaxf(sacc[ni][2], sacc[ni][3]));
        }
        mx0 = fmaxf(mx0, __shfl_xor_sync(0xffffffffu, mx0, 1));
        mx0 = fmaxf(mx0, __shfl_xor_sync(0xffffffffu, mx0, 2));
        mx1 = fmaxf(mx1, __shfl_xor_sync(0xffffffffu, mx1, 1));
        mx1 = fmaxf(mx1, __shfl_xor_sync(0xffffffffu, mx1, 2));
        const float mn0 = fmaxf(m_i0, mx0), mn1 = fmaxf(m_i1, mx1);
        const float c0 = ex2(m_i0 - mn0), c1 = ex2(m_i1 - mn1);
        m_i0 = mn0; m_i1 = mn1;
        float rs0 = 0.f, rs1 = 0.f;
        uint32_t pfrag[16][2];
        #pragma unroll
        for (int ni = 0; ni < 16; ++ni) {
            const float p0 = ex2(sacc[ni][0] - mn0);
            const float p1 = ex2(sacc[ni][1] - mn0);
            const float p2 = ex2(sacc[ni][2] - mn1);
            const float p3 = ex2(sacc[ni][3] - mn1);
            rs0 += p0 + p1; rs1 += p2 + p3;
            __half2 h0 = __floats2half2_rn(p0, p1);
            __half2 h1 = __floats2half2_rn(p2, p3);
            pfrag[ni][0] = *reinterpret_cast<uint32_t*>(&h0);
            pfrag[ni][1] = *reinterpret_cast<uint32_t*>(&h1);
        }
        rs0 += __shfl_xor_sync(0xffffffffu, rs0, 1);
        rs0 += __shfl_xor_sync(0xffffffffu, rs0, 2);
        rs1 += __shfl_xor_sync(0xffffffffu, rs1, 1);
        rs1 += __shfl_xor_sync(0xffffffffu, rs1, 2);
        l_i0 = l_i0 * c0 + rs0;
        l_i1 = l_i1 * c1 + rs1;
        #pragma unroll
        for (int nc = 0; nc < 8; ++nc) {
            oacc[nc][0] *= c0; oacc[nc][1] *= c0;
            oacc[nc][2] *= c1; oacc[nc][3] *= c1;
        }

        // ---- O += P Vh^T (s-dim 128 = 8 k-steps of 16)
        #pragma unroll
        for (int ks = 0; ks < 8; ++ks) {
            const uint32_t pa[4] = { pfrag[2 * ks][0], pfrag[2 * ks][1],
                                     pfrag[2 * ks + 1][0], pfrag[2 * ks + 1][1] };
            #pragma unroll
            for (int nj = 0; nj < 4; ++nj) {
                uint32_t vb4[4];
                ldsm4(vb4, st + ((9216 + (nj * 16 + nRow) * VP) + ks * 16 + nK) * 2);
                mma16816(oacc[nj * 2 + 0], pa, vb4[0], vb4[1]);
                mma16816(oacc[nj * 2 + 1], pa, vb4[2], vb4[3]);
            }
        }

        // all reads of stage (kb & 1) complete before it is overwritten
        __syncthreads();
        if (kb < 6) { issueKV(kb + 2); CP_COMMIT(); }
    }

    // ---- epilogue: store fp16 h, [b][t][c]
    const float inv0 = 1.f / l_i0, inv1 = 1.f / l_i1;
    #pragma unroll
    for (int nc = 0; nc < 8; ++nc) {
        const size_t off0 = ((size_t)b * TT + t0 + wid * 16 + g) * CH
                          + head * 64 + nc * 8 + tig * 2;
        __half2 h0 = __floats2half2_rn(oacc[nc][0] * inv0, oacc[nc][1] * inv0);
        *(__half2*)(g_hh + off0) = h0;
        const size_t off1 = off0 + (size_t)8 * CH;
        __half2 h1 = __floats2half2_rn(oacc[nc][2] * inv1, oacc[nc][3] * inv1);
        *(__half2*)(g_hh + off1) = h1;
    }
}

// ---------------- launch ----------------------------------------------------------
extern "C" void kernel_launch(void* const* d_in, const int* in_sizes, int n_in,
                              void* d_out, int out_size) {
    const float* x    = (const float*)d_in[0];
    const float* nw   = (const float*)d_in[1];
    const float* nb   = (const float*)d_in[2];
    const float* qkvw = (const float*)d_in[3];
    const float* qkvb = (const float*)d_in[4];
    const float* pw   = (const float*)d_in[5];
    const float* pb   = (const float*)d_in[6];
    float* out = (float*)d_out;

    cudaFuncSetAttribute(hgemm_kernel<false>,
                         cudaFuncAttributeMaxDynamicSharedMemorySize, GEMM_SMEM);
    cudaFuncSetAttribute(hgemm_kernel<true>,
                         cudaFuncAttributeMaxDynamicSharedMemorySize, GEMM_SMEM);
    cudaFuncSetAttribute(attn_kernel,
                         cudaFuncAttributeMaxDynamicSharedMemorySize, ATTN_SMEM);

    init_pack_kernel<<<512 + 2048, 256>>>(x, qkvw, pw);
    x_pack_kernel<<<dim3(16, 8, 16), 256>>>(x, nw, nb);
    hgemm_kernel<false><<<dim3(8, 12, BATCH), 256, GEMM_SMEM>>>(qkvb, nullptr, nullptr);
    attn_kernel<<<dim3(8, NHEAD, BATCH), 256, ATTN_SMEM>>>();
    hgemm_kernel<true><<<dim3(8, 4, BATCH), 256, GEMM_SMEM>>>(pb, x, out);
}